// round 14
// baseline (speedup 1.0000x reference)
#include <cuda_runtime.h>
#include <cuda_bf16.h>
#include <cstdint>
#include <cstddef>

#define NNODES 3000
#define NFEAT 2
#define NUNITS 64
#define BATCH 16
#define CCH (NFEAT + NUNITS)       // 66
#define NCOLS (CCH * BATCH)        // 1056
#define NGATE (2 * NUNITS)         // 128
#define HXSZ (NNODES * NUNITS)

#define KPAD 3008                  // 47 * 64
#define MPAD 1152
#define NPADS 3072
#define NCHUNK 47
#define MT 128
#define NT 256

#if defined(__CUDA_ARCH_FEAT_SM103_ALL) || defined(__CUDA_ARCH_FEAT_SM100_ALL) || \
    (defined(__CUDA_ARCH_SPECIFIC__) && (__CUDA_ARCH_SPECIFIC__ >= 1000))
#define HAS_TCGEN05 1
#else
#define HAS_TCGEN05 0
#endif

#define MMA_IDESC ((1u<<4)|(1u<<7)|(1u<<10)|((NT/8)<<17)|((MT/16)<<24))

__device__ __nv_bfloat16 g_S0h[(size_t)NPADS * KPAD];
__device__ __nv_bfloat16 g_S0l[(size_t)NPADS * KPAD];
__device__ __nv_bfloat16 g_S1h[(size_t)NPADS * KPAD];
__device__ __nv_bfloat16 g_S1l[(size_t)NPADS * KPAD];
__device__ __nv_bfloat16 g_X0Th[(size_t)MPAD * KPAD];
__device__ __nv_bfloat16 g_X0Tl[(size_t)MPAD * KPAD];
__device__ __nv_bfloat16 g_X1aTh[(size_t)MPAD * KPAD];
__device__ __nv_bfloat16 g_X1aTl[(size_t)MPAD * KPAD];
__device__ __nv_bfloat16 g_X1bTh[(size_t)MPAD * KPAD];
__device__ __nv_bfloat16 g_X1bTl[(size_t)MPAD * KPAD];
__device__ float g_X0[(size_t)NNODES * NCOLS];
__device__ float g_X1a[(size_t)NNODES * NCOLS];
__device__ float g_X2a[(size_t)NNODES * NCOLS];
__device__ float g_X1b[(size_t)NNODES * NCOLS];
__device__ float g_X2b[(size_t)NNODES * NCOLS];
__device__ float g_invdr[NNODES];
__device__ float g_dcol[NNODES];
__device__ float g_invdc[NNODES];
__device__ float g_u[(size_t)BATCH * NNODES * NUNITS];

__device__ __forceinline__ uint32_t smem_u32(const void* p) {
    uint32_t a;
    asm("{ .reg .u64 t; cvta.to.shared.u64 t, %1; cvt.u32.u64 %0, t; }" : "=r"(a) : "l"(p));
    return a;
}
static __device__ __forceinline__ uint32_t sw128(uint32_t off) { return off ^ ((off >> 3) & 0x70); }
static __device__ __forceinline__ void split_bf16(float v, __nv_bfloat16& h, __nv_bfloat16& l) {
    h = __float2bfloat16(v);
    l = __float2bfloat16(v - __bfloat162float(h));
}

#define CP_ASYNC16(dst, src) \
    asm volatile("cp.async.cg.shared.global [%0], [%1], 16;" :: "r"(dst), "l"(src) : "memory")
#define CP_COMMIT() asm volatile("cp.async.commit_group;" ::: "memory")
#define CP_WAIT1()  asm volatile("cp.async.wait_group 1;" ::: "memory")
#define CP_WAIT0()  asm volatile("cp.async.wait_group 0;" ::: "memory")

#if HAS_TCGEN05
__device__ __forceinline__ uint32_t elect_one() {
    uint32_t pred;
    asm volatile("{\n\t.reg .pred p;\n\telect.sync _|p, 0xFFFFFFFF;\n\tselp.b32 %0, 1, 0, p;\n\t}"
                 : "=r"(pred));
    return pred;
}
#define MBAR_INIT(a, c) asm volatile("mbarrier.init.shared.b64 [%0], %1;" :: "r"(a), "r"(c) : "memory")
#define MBAR_INVAL(a)   asm volatile("mbarrier.inval.shared.b64 [%0];" :: "r"(a) : "memory")
__device__ __forceinline__ void mbar_wait(uint32_t addr, uint32_t parity) {
    uint32_t done;
    asm volatile("{\n\t.reg .pred p;\n\t"
                 "mbarrier.try_wait.parity.acquire.cta.shared::cta.b64 p, [%1], %2;\n\t"
                 "selp.b32 %0, 1, 0, p;\n\t}"
                 : "=r"(done) : "r"(addr), "r"(parity) : "memory");
    if (!done) {
        asm volatile("{\n\t.reg .pred P1;\n\t"
                     "WL_%=:\n\t"
                     "mbarrier.try_wait.parity.acquire.cta.shared::cta.b64 P1, [%0], %1, 0x989680;\n\t"
                     "@P1 bra.uni WD_%=;\n\t"
                     "bra.uni WL_%=;\n\t"
                     "WD_%=:\n\t}"
                     :: "r"(addr), "r"(parity) : "memory");
    }
}
#define TC_ALLOC(sm, n)   asm volatile("tcgen05.alloc.cta_group::1.sync.aligned.shared::cta.b32 [%0], %1;" :: "r"(sm), "r"(n) : "memory")
#define TC_DEALLOC(t, n)  asm volatile("tcgen05.dealloc.cta_group::1.sync.aligned.b32 %0, %1;" :: "r"(t), "r"(n))
#define TC_RELINQ()       asm volatile("tcgen05.relinquish_alloc_permit.cta_group::1.sync.aligned;")
#define TC_COMMIT(mb)     asm volatile("tcgen05.commit.cta_group::1.mbarrier::arrive::one.shared::cluster.b64 [%0];" :: "r"(mb) : "memory")
#define TC_FENCE_AFTER()  asm volatile("tcgen05.fence::after_thread_sync;" ::: "memory")
#define TC_WAIT_LD()      asm volatile("tcgen05.wait::ld.sync.aligned;" ::: "memory")
#define FENCE_ASYNC()     asm volatile("fence.proxy.async.shared::cta;" ::: "memory")

__device__ __forceinline__ void mma_f16_ss(uint32_t d, uint64_t a, uint64_t b,
                                           uint32_t idesc, uint32_t en) {
    asm volatile("{\n\t.reg .pred p;\n\tsetp.ne.u32 p, %4, 0;\n\t"
                 "tcgen05.mma.cta_group::1.kind::f16 [%0], %1, %2, %3, {%5,%5,%5,%5}, p;\n\t}"
                 :: "r"(d), "l"(a), "l"(b), "r"(idesc), "r"(en), "r"(0u) : "memory");
}

#define LDTM_X32(r, addr) \
    asm volatile("tcgen05.ld.sync.aligned.32x32b.x32.b32 " \
        "{%0,%1,%2,%3,%4,%5,%6,%7,%8,%9,%10,%11,%12,%13,%14,%15," \
        "%16,%17,%18,%19,%20,%21,%22,%23,%24,%25,%26,%27,%28,%29,%30,%31}, [%32];" \
        : "=r"((r)[0]),"=r"((r)[1]),"=r"((r)[2]),"=r"((r)[3]),"=r"((r)[4]),"=r"((r)[5]), \
          "=r"((r)[6]),"=r"((r)[7]),"=r"((r)[8]),"=r"((r)[9]),"=r"((r)[10]),"=r"((r)[11]), \
          "=r"((r)[12]),"=r"((r)[13]),"=r"((r)[14]),"=r"((r)[15]),"=r"((r)[16]),"=r"((r)[17]), \
          "=r"((r)[18]),"=r"((r)[19]),"=r"((r)[20]),"=r"((r)[21]),"=r"((r)[22]),"=r"((r)[23]), \
          "=r"((r)[24]),"=r"((r)[25]),"=r"((r)[26]),"=r"((r)[27]),"=r"((r)[28]),"=r"((r)[29]), \
          "=r"((r)[30]),"=r"((r)[31]) : "r"(addr))

static __device__ __forceinline__ uint64_t make_desc(uint32_t addr) {
    const uint64_t base = (uint64_t(2) << 61) | (uint64_t(1) << 46) |
                          (uint64_t(64) << 32) | (uint64_t(1) << 16);
    return base | ((uint64_t)(addr >> 4) & 0x3FFF);
}
#else
__device__ __forceinline__ void ldm4(uint32_t* r, uint32_t addr) {
    asm volatile("ldmatrix.sync.aligned.m8n8.x4.shared.b16 {%0,%1,%2,%3}, [%4];"
                 : "=r"(r[0]), "=r"(r[1]), "=r"(r[2]), "=r"(r[3]) : "r"(addr));
}
__device__ __forceinline__ void mma16816(float* c, const uint32_t* a, uint32_t b0, uint32_t b1) {
    asm volatile("mma.sync.aligned.m16n8k16.row.col.f32.bf16.bf16.f32 "
                 "{%0,%1,%2,%3}, {%4,%5,%6,%7}, {%8,%9}, {%0,%1,%2,%3};"
                 : "+f"(c[0]), "+f"(c[1]), "+f"(c[2]), "+f"(c[3])
                 : "r"(a[0]), "r"(a[1]), "r"(a[2]), "r"(a[3]), "r"(b0), "r"(b1));
}
#endif

// ---------------- degree kernels (R4) ----------------
__global__ void k_rowsum(const float* __restrict__ A, float* __restrict__ invdr) {
    __shared__ float red[256];
    int r = blockIdx.x;
    float s = 0.f;
    for (int j = threadIdx.x; j < NNODES; j += 256) s += A[(size_t)r * NNODES + j];
    red[threadIdx.x] = s;
    __syncthreads();
    for (int w = 128; w > 0; w >>= 1) {
        if (threadIdx.x < w) red[threadIdx.x] += red[threadIdx.x + w];
        __syncthreads();
    }
    if (threadIdx.x == 0) {
        float d = red[0];
        invdr[r] = (d > 0.f) ? 1.f / d : 0.f;
    }
}
__global__ void k_zero_dcol(float* __restrict__ dcol) {
    int j = blockIdx.x * blockDim.x + threadIdx.x;
    if (j < NNODES) dcol[j] = 0.f;
}
__global__ void k_colsum_part(const float* __restrict__ A, float* __restrict__ dcol) {
    int j = blockIdx.x * blockDim.x + threadIdx.x;
    if (j >= NNODES) return;
    int r0 = blockIdx.y * 125;
    float s = 0.f;
    for (int r = r0; r < r0 + 125; r++) s += A[(size_t)r * NNODES + j];
    atomicAdd(&dcol[j], s);
}
__global__ void k_invert_dcol(const float* __restrict__ dcol, float* __restrict__ invdc) {
    int j = blockIdx.x * blockDim.x + threadIdx.x;
    if (j < NNODES) {
        float d = dcol[j];
        invdc[j] = (d > 0.f) ? 1.f / d : 0.f;
    }
}

// ---------------- supports (R4) ----------------
__global__ void k_buildS0_split(const float* __restrict__ A, const float* __restrict__ invdr,
                                __nv_bfloat16* __restrict__ Sh, __nv_bfloat16* __restrict__ Sl) {
    __shared__ float sm[32][33];
    int i0 = blockIdx.x * 32;
    int j0 = blockIdx.y * 32;
    int tx = threadIdx.x, ty = threadIdx.y;
#pragma unroll
    for (int r = 0; r < 4; r++) {
        int j = j0 + ty + r * 8;
        int i = i0 + tx;
        sm[ty + r * 8][tx] = (j < NNODES && i < NNODES) ? A[(size_t)j * NNODES + i] : 0.f;
    }
    __syncthreads();
#pragma unroll
    for (int r = 0; r < 4; r++) {
        int i = i0 + ty + r * 8;
        int j = j0 + tx;
        if (i < NPADS && j < KPAD) {
            float v = (i < NNODES && j < NNODES) ? sm[tx][ty + r * 8] * invdr[j] : 0.f;
            __nv_bfloat16 h, l;
            split_bf16(v, h, l);
            Sh[(size_t)i * KPAD + j] = h;
            Sl[(size_t)i * KPAD + j] = l;
        }
    }
}
__global__ void k_buildS1_split(const float* __restrict__ A, const float* __restrict__ invdc,
                                __nv_bfloat16* __restrict__ Sh, __nv_bfloat16* __restrict__ Sl) {
    int j = blockIdx.x * blockDim.x + threadIdx.x;
    int i = blockIdx.y;
    if (j >= KPAD) return;
    float v = (i < NNODES && j < NNODES) ? A[(size_t)i * NNODES + j] * invdc[j] : 0.f;
    __nv_bfloat16 h, l;
    split_bf16(v, h, l);
    Sh[(size_t)i * KPAD + j] = h;
    Sl[(size_t)i * KPAD + j] = l;
}

// ---------------- X0 builders (R4, input-first channel order) ----------------
__global__ void k_buildX0(const float* __restrict__ inputs, const float* __restrict__ hx,
                          float* __restrict__ X0) {
    size_t total = (size_t)NNODES * NCOLS;
    for (size_t idx = (size_t)blockIdx.x * blockDim.x + threadIdx.x; idx < total;
         idx += (size_t)gridDim.x * blockDim.x) {
        int n = (int)(idx / NCOLS);
        int r = (int)(idx - (size_t)n * NCOLS);
        int c = r >> 4;
        int b = r & 15;
        float v = (c < NFEAT) ? inputs[(size_t)b * (NNODES * NFEAT) + n * NFEAT + c]
                              : hx[(size_t)b * HXSZ + n * NUNITS + (c - NFEAT)];
        X0[idx] = v;
    }
}
__global__ void k_buildX0T(const float* __restrict__ inputs, const float* __restrict__ hx,
                           __nv_bfloat16* __restrict__ Th, __nv_bfloat16* __restrict__ Tl) {
    size_t total = (size_t)MPAD * KPAD;
    for (size_t idx = (size_t)blockIdx.x * blockDim.x + threadIdx.x; idx < total;
         idx += (size_t)gridDim.x * blockDim.x) {
        int r = (int)(idx / KPAD);
        int n = (int)(idx - (size_t)r * KPAD);
        float v = 0.f;
        if (r < NCOLS && n < NNODES) {
            int c = r >> 4;
            int b = r & 15;
            v = (c < NFEAT) ? inputs[(size_t)b * (NNODES * NFEAT) + n * NFEAT + c]
                            : hx[(size_t)b * HXSZ + n * NUNITS + (c - NFEAT)];
        }
        __nv_bfloat16 h, l;
        split_bf16(v, h, l);
        Th[idx] = h;
        Tl[idx] = l;
    }
}
#define PADELEMS ((MPAD - NCOLS) * KPAD + NCOLS * 8)
__global__ void k_zero_padsT(__nv_bfloat16* a, __nv_bfloat16* b,
                             __nv_bfloat16* c, __nv_bfloat16* d) {
    int idx = blockIdx.x * blockDim.x + threadIdx.x;
    if (idx >= PADELEMS) return;
    size_t off;
    if (idx < (MPAD - NCOLS) * KPAD) {
        int r = NCOLS + idx / KPAD;
        int col = idx % KPAD;
        off = (size_t)r * KPAD + col;
    } else {
        int k = idx - (MPAD - NCOLS) * KPAD;
        int r = k >> 3;
        int col = NNODES + (k & 7);
        off = (size_t)r * KPAD + col;
    }
    __nv_bfloat16 z = __float2bfloat16(0.f);
    a[off] = z; b[off] = z; c[off] = z; d[off] = z;
}

// ---------------- main tensor-core GEMM (R4 config, verbatim) ----------------
#define ST_AH 0
#define ST_AL 16384
#define ST_BH 32768
#define ST_BL 65536
#define STAGE_SZ 98304
#define SMEM_DYN (2 * STAGE_SZ)
#define SST 264

__global__ __launch_bounds__(256, 1)
void k_gemm_tc(const __nv_bfloat16* __restrict__ Ah0, const __nv_bfloat16* __restrict__ Al0,
               const __nv_bfloat16* __restrict__ Ah1, const __nv_bfloat16* __restrict__ Al1,
               const __nv_bfloat16* __restrict__ Bh0, const __nv_bfloat16* __restrict__ Bl0,
               const __nv_bfloat16* __restrict__ Bh1, const __nv_bfloat16* __restrict__ Bl1,
               const float* __restrict__ Xprev,
               float* __restrict__ Yf0, float* __restrict__ Yf1,
               __nv_bfloat16* __restrict__ YTh0, __nv_bfloat16* __restrict__ YTl0,
               __nv_bfloat16* __restrict__ YTh1, __nv_bfloat16* __restrict__ YTl1,
               float alpha, float beta) {
    extern __shared__ __align__(1024) unsigned char dynsm[];
    const int t = threadIdx.x;
    const int m0 = blockIdx.y * MT;
    const int n0 = blockIdx.x * NT;
    const int z = blockIdx.z;
    const uint32_t dyn_u32 = smem_u32(dynsm);

    const __nv_bfloat16* Ahg = (z ? Ah1 : Ah0) + (size_t)m0 * KPAD;
    const __nv_bfloat16* Alg = (z ? Al1 : Al0) + (size_t)m0 * KPAD;
    const __nv_bfloat16* Bhg = (z ? Bh1 : Bh0) + (size_t)n0 * KPAD;
    const __nv_bfloat16* Blg = (z ? Bl1 : Bl0) + (size_t)n0 * KPAD;
    float* Yf = z ? Yf1 : Yf0;
    __nv_bfloat16* YTh = z ? YTh1 : YTh0;
    __nv_bfloat16* YTl = z ? YTl1 : YTl0;

    auto load_chunk = [&](int ck, uint32_t stg) {
        const int kb = ck * 64;
#pragma unroll
        for (int i = 0; i < 4; i++) {
            int idx = t + i * 256;
            int row = idx >> 3, seg = idx & 7;
            size_t go = (size_t)row * KPAD + kb + seg * 8;
            uint32_t so = sw128((uint32_t)(row * 128 + seg * 16));
            CP_ASYNC16(dyn_u32 + stg + ST_AH + so, Ahg + go);
            CP_ASYNC16(dyn_u32 + stg + ST_AL + so, Alg + go);
        }
#pragma unroll
        for (int i = 0; i < 8; i++) {
            int idx = t + i * 256;
            int row = idx >> 3, seg = idx & 7;
            size_t go = (size_t)row * KPAD + kb + seg * 8;
            uint32_t so = sw128((uint32_t)(row * 128 + seg * 16));
            CP_ASYNC16(dyn_u32 + stg + ST_BH + so, Bhg + go);
            CP_ASYNC16(dyn_u32 + stg + ST_BL + so, Blg + go);
        }
        CP_COMMIT();
    };

#if HAS_TCGEN05
    __shared__ uint32_t s_tmem;
    __shared__ __align__(8) uint64_t s_mbar[2];
    const uint32_t mbar0 = smem_u32(&s_mbar[0]);
    const uint32_t mbar1 = smem_u32(&s_mbar[1]);

    if ((t >> 5) == 0) TC_ALLOC(smem_u32(&s_tmem), 256);
    if (t == 0) {
        MBAR_INIT(mbar0, 1);
        MBAR_INIT(mbar1, 1);
    }
    __syncthreads();
    const uint32_t tmem = s_tmem;

    load_chunk(0, 0);
    load_chunk(1, STAGE_SZ);

    for (int k = 0; k < NCHUNK; k++) {
        const int s = k & 1;
        const uint32_t stage = s ? STAGE_SZ : 0;
        if (k == NCHUNK - 1) { CP_WAIT0(); } else { CP_WAIT1(); }
        __syncthreads();
        if ((t >> 5) == 0) {
            FENCE_ASYNC();
            if (elect_one()) {
                uint64_t dAh = make_desc(dyn_u32 + stage + ST_AH);
                uint64_t dAl = make_desc(dyn_u32 + stage + ST_AL);
                uint64_t dBh = make_desc(dyn_u32 + stage + ST_BH);
                uint64_t dBl = make_desc(dyn_u32 + stage + ST_BL);
#pragma unroll
                for (int ks = 0; ks < 4; ks++)
                    mma_f16_ss(tmem, dAh + ks * 2, dBh + ks * 2, MMA_IDESC,
                               (k != 0 || ks != 0) ? 1u : 0u);
#pragma unroll
                for (int ks = 0; ks < 4; ks++)
                    mma_f16_ss(tmem, dAh + ks * 2, dBl + ks * 2, MMA_IDESC, 1u);
#pragma unroll
                for (int ks = 0; ks < 4; ks++)
                    mma_f16_ss(tmem, dAl + ks * 2, dBh + ks * 2, MMA_IDESC, 1u);
                TC_COMMIT(s ? mbar1 : mbar0);
            }
        }
        if (k + 2 < NCHUNK) {
            mbar_wait(s ? mbar1 : mbar0, (k >> 1) & 1);
            load_chunk(k + 2, stage);
        }
    }
    mbar_wait(mbar0, 1);
    mbar_wait(mbar1, 0);
    TC_FENCE_AFTER();
    __syncthreads();

    const bool doT = (YTh != nullptr);
    const int w = t >> 5;
    const int chal = w >> 2;
    const int lane = t & 31;
    const int rl = (w & 3) * 32 + lane;
    const int m = m0 + rl;
    const bool vm = (m < NCOLS);
    __nv_bfloat16* shh = (__nv_bfloat16*)dynsm;
    __nv_bfloat16* shl = shh + 128 * SST;

    for (int cb = 0; cb < 4; cb++) {
        const int c0 = chal * 128 + cb * 32;
        uint32_t regs[32];
        LDTM_X32(regs, tmem + c0);
        TC_WAIT_LD();
#pragma unroll
        for (int j = 0; j < 32; j++) {
            int n = n0 + c0 + j;
            float y = alpha * __uint_as_float(regs[j]);
            bool vn = (n < NNODES);
            if (beta != 0.f && vm && vn) y += beta * Xprev[(size_t)n * NCOLS + m];
            if (vm && vn) Yf[(size_t)n * NCOLS + m] = y;
            if (doT) {
                __nv_bfloat16 h, l;
                split_bf16(y, h, l);
                shh[rl * SST + c0 + j] = h;
                shl[rl * SST + c0 + j] = l;
            }
        }
    }
    if (doT) {
        __syncthreads();
        int r = t >> 1, half = t & 1;
        int m2 = m0 + r;
        if (m2 < NCOLS) {
#pragma unroll
            for (int v = 0; v < 16; v++) {
                int nn = n0 + half * 128 + v * 8;
                int sidx = r * SST + half * 128 + v * 8;
                if (nn + 8 <= NNODES) {
                    *(uint4*)(YTh + (size_t)m2 * KPAD + nn) = *(uint4*)&shh[sidx];
                    *(uint4*)(YTl + (size_t)m2 * KPAD + nn) = *(uint4*)&shl[sidx];
                } else {
                    for (int e = 0; e < 8; e++)
                        if (nn + e < NNODES) {
                            YTh[(size_t)m2 * KPAD + nn + e] = shh[sidx + e];
                            YTl[(size_t)m2 * KPAD + nn + e] = shl[sidx + e];
                        }
                }
            }
        }
    }
    __syncthreads();
    if (t == 0) { MBAR_INVAL(mbar0); MBAR_INVAL(mbar1); }
    __syncthreads();
    if ((t >> 5) == 0) {
        TC_RELINQ();
        TC_DEALLOC(tmem, 256);
    }
#else
    const int lane = t & 31;
    const int warp = t >> 5;
    const int wm = warp & 1;
    const int wn = warp >> 1;
    const int lg = lane >> 3, lr = lane & 7;

    float acc[4][8][4];
#pragma unroll
    for (int i = 0; i < 4; i++)
#pragma unroll
        for (int j = 0; j < 8; j++)
#pragma unroll
            for (int e = 0; e < 4; e++) acc[i][j][e] = 0.f;

    for (int chunk = 0; chunk < NCHUNK; chunk++) {
        load_chunk(chunk, 0);
        CP_WAIT0();
        __syncthreads();
#pragma unroll
        for (int ks = 0; ks < 4; ks++) {
            uint32_t ah[4][4], al[4][4];
#pragma unroll
            for (int am = 0; am < 4; am++) {
                int row = wm * 64 + am * 16 + (lg & 1) * 8 + lr;
                int koff = ks * 32 + (lg >> 1) * 16;
                uint32_t so = sw128((uint32_t)(row * 128 + koff));
                ldm4(ah[am], dyn_u32 + ST_AH + so);
                ldm4(al[am], dyn_u32 + ST_AL + so);
            }
            uint32_t bh[4][4], bl[4][4];
#pragma unroll
            for (int p = 0; p < 4; p++) {
                int row = wn * 64 + p * 16 + (lg >> 1) * 8 + lr;
                int koff = ks * 32 + (lg & 1) * 16;
                uint32_t so = sw128((uint32_t)(row * 128 + koff));
                ldm4(bh[p], dyn_u32 + ST_BH + so);
                ldm4(bl[p], dyn_u32 + ST_BL + so);
            }
#pragma unroll
            for (int am = 0; am < 4; am++)
#pragma unroll
                for (int an = 0; an < 8; an++) {
                    int p = an >> 1, h = (an & 1) * 2;
                    mma16816(acc[am][an], ah[am], bh[p][h], bh[p][h + 1]);
                    mma16816(acc[am][an], ah[am], bl[p][h], bl[p][h + 1]);
                    mma16816(acc[am][an], al[am], bh[p][h], bh[p][h + 1]);
                }
        }
        __syncthreads();
    }

    const bool doT = (YTh != nullptr);
#pragma unroll
    for (int am = 0; am < 4; am++) {
#pragma unroll
        for (int an = 0; an < 8; an++) {
            int mrow = m0 + wm * 64 + am * 16 + (lane >> 2);
            int ncol = n0 + wn * 64 + an * 8 + (lane & 3) * 2;
#pragma unroll
            for (int h = 0; h < 2; h++) {
                int m = mrow + h * 8;
                if (m >= NCOLS) continue;
#pragma unroll
                for (int e = 0; e < 2; e++) {
                    int n = ncol + e;
                    if (n >= NNODES) continue;
                    float y = alpha * acc[am][an][h * 2 + e];
                    if (beta != 0.f) y += beta * Xprev[(size_t)n * NCOLS + m];
                    Yf[(size_t)n * NCOLS + m] = y;
                    if (doT) {
                        __nv_bfloat16 hh, ll;
                        split_bf16(y, hh, ll);
                        YTh[(size_t)m * KPAD + n] = hh;
                        YTl[(size_t)m * KPAD + n] = ll;
                    }
                }
            }
        }
    }
#endif
}

// ---------------- gate projection: 2 nodes per block (W reuse) ----------------
__global__ void k_proj_gate(const float* __restrict__ Wg, const float* __restrict__ bg,
                            const float* __restrict__ hx,
                            const float* __restrict__ X0, const float* __restrict__ X1a,
                            const float* __restrict__ X2a, const float* __restrict__ X1b,
                            const float* __restrict__ X2b,
                            float* __restrict__ X0w,
                            __nv_bfloat16* __restrict__ X0Th, __nv_bfloat16* __restrict__ X0Tl,
                            float* __restrict__ ubuf) {
    __shared__ float sx[2][5][NCOLS];
    int n0 = blockIdx.x * 2;
    const float* mats[5] = {X0, X1a, X2a, X1b, X2b};
    for (int tt = threadIdx.x; tt < 2 * 5 * NCOLS; tt += blockDim.x) {
        int nl = tt / (5 * NCOLS);
        int r = tt - nl * 5 * NCOLS;
        int m = r / NCOLS;
        int idx = r - m * NCOLS;
        sx[nl][m][idx] = mats[m][(size_t)(n0 + nl) * NCOLS + idx];
    }
    __syncthreads();

    int o = threadIdx.x;
    float acc[2][BATCH];
#pragma unroll
    for (int nl = 0; nl < 2; nl++)
#pragma unroll
        for (int b = 0; b < BATCH; b++) acc[nl][b] = bg[o];
    for (int c = 0; c < CCH; c++) {
#pragma unroll
        for (int m = 0; m < 5; m++) {
            float w = Wg[(size_t)(c * 5 + m) * NGATE + o];
#pragma unroll
            for (int nl = 0; nl < 2; nl++)
#pragma unroll
                for (int b = 0; b < BATCH; b++)
                    acc[nl][b] += sx[nl][m][c * 16 + b] * w;
        }
    }
#pragma unroll
    for (int nl = 0; nl < 2; nl++) {
        int n = n0 + nl;
#pragma unroll
        for (int b = 0; b < BATCH; b++) {
            float s = 1.f / (1.f + __expf(-acc[nl][b]));
            if (o < NUNITS) {
                float h = hx[(size_t)b * HXSZ + n * NUNITS + o];
                float rh = s * h;
                X0w[(size_t)n * NCOLS + (NFEAT + o) * 16 + b] = rh;
                int rr = (NFEAT + o) * 16 + b;
                __nv_bfloat16 hi, lo;
                split_bf16(rh, hi, lo);
                X0Th[(size_t)rr * KPAD + n] = hi;
                X0Tl[(size_t)rr * KPAD + n] = lo;
            } else {
                ubuf[(size_t)b * HXSZ + n * NUNITS + (o - NUNITS)] = s;
            }
        }
    }
}

// ---------------- cand projection + GRU combine: 2 nodes per block ----------------
__global__ void k_proj_cand(const float* __restrict__ Wc, const float* __restrict__ bc,
                            const float* __restrict__ hx, const float* __restrict__ ubuf,
                            const float* __restrict__ X0, const float* __restrict__ X1a,
                            const float* __restrict__ X2a, const float* __restrict__ X1b,
                            const float* __restrict__ X2b,
                            float* __restrict__ out) {
    __shared__ float sx[2][5][NCOLS];
    int n0 = blockIdx.x * 2;
    const float* mats[5] = {X0, X1a, X2a, X1b, X2b};
    for (int tt = threadIdx.x; tt < 2 * 5 * NCOLS; tt += blockDim.x) {
        int nl = tt / (5 * NCOLS);
        int r = tt - nl * 5 * NCOLS;
        int m = r / NCOLS;
        int idx = r - m * NCOLS;
        sx[nl][m][idx] = mats[m][(size_t)(n0 + nl) * NCOLS + idx];
    }
    __syncthreads();

    int o = threadIdx.x;
    float acc[2][BATCH];
#pragma unroll
    for (int nl = 0; nl < 2; nl++)
#pragma unroll
        for (int b = 0; b < BATCH; b++) acc[nl][b] = bc[o];
    for (int c = 0; c < CCH; c++) {
#pragma unroll
        for (int m = 0; m < 5; m++) {
            float w = Wc[(size_t)(c * 5 + m) * NUNITS + o];
#pragma unroll
            for (int nl = 0; nl < 2; nl++)
#pragma unroll
                for (int b = 0; b < BATCH; b++)
                    acc[nl][b] += sx[nl][m][c * 16 + b] * w;
        }
    }
#pragma unroll
    for (int nl = 0; nl < 2; nl++) {
        int n = n0 + nl;
#pragma unroll
        for (int b = 0; b < BATCH; b++) {
            float cc = tanhf(acc[nl][b]);
            size_t i = (size_t)b * HXSZ + n * NUNITS + o;
            float u = ubuf[i];
            float h = hx[i];
            out[i] = u * h + (1.f - u) * cc;
        }
    }
}

// ---------------- launch ----------------
extern "C" void kernel_launch(void* const* d_in, const int* in_sizes, int n_in,
                              void* d_out, int out_size) {
    const float* inputs = (const float*)d_in[0];
    const float* hx     = (const float*)d_in[1];
    const float* adj    = (const float*)d_in[2];
    const float* Wg     = (const float*)d_in[3];
    const float* bg     = (const float*)d_in[4];
    const float* Wc     = (const float*)d_in[5];
    const float* bc     = (const float*)d_in[6];
    float* out = (float*)d_out;

    __nv_bfloat16 *S0h, *S0l, *S1h, *S1l, *X0Th, *X0Tl, *X1aTh, *X1aTl, *X1bTh, *X1bTl;
    float *X0, *X1a, *X2a, *X1b, *X2b, *invdr, *dcol, *invdc, *ubuf;
    cudaGetSymbolAddress((void**)&S0h, g_S0h);
    cudaGetSymbolAddress((void**)&S0l, g_S0l);
    cudaGetSymbolAddress((void**)&S1h, g_S1h);
    cudaGetSymbolAddress((void**)&S1l, g_S1l);
    cudaGetSymbolAddress((void**)&X0Th, g_X0Th);
    cudaGetSymbolAddress((void**)&X0Tl, g_X0Tl);
    cudaGetSymbolAddress((void**)&X1aTh, g_X1aTh);
    cudaGetSymbolAddress((void**)&X1aTl, g_X1aTl);
    cudaGetSymbolAddress((void**)&X1bTh, g_X1bTh);
    cudaGetSymbolAddress((void**)&X1bTl, g_X1bTl);
    cudaGetSymbolAddress((void**)&X0, g_X0);
    cudaGetSymbolAddress((void**)&X1a, g_X1a);
    cudaGetSymbolAddress((void**)&X2a, g_X2a);
    cudaGetSymbolAddress((void**)&X1b, g_X1b);
    cudaGetSymbolAddress((void**)&X2b, g_X2b);
    cudaGetSymbolAddress((void**)&invdr, g_invdr);
    cudaGetSymbolAddress((void**)&dcol, g_dcol);
    cudaGetSymbolAddress((void**)&invdc, g_invdc);
    cudaGetSymbolAddress((void**)&ubuf, g_u);

    cudaFuncSetAttribute(k_gemm_tc, cudaFuncAttributeMaxDynamicSharedMemorySize, SMEM_DYN);

    k_rowsum<<<NNODES, 256>>>(adj, invdr);
    k_zero_dcol<<<(NNODES + 255) / 256, 256>>>(dcol);
    {
        dim3 g((NNODES + 255) / 256, 24);
        k_colsum_part<<<g, 256>>>(adj, dcol);
    }
    k_invert_dcol<<<(NNODES + 255) / 256, 256>>>(dcol, invdc);

    {
        dim3 g(NPADS / 32, KPAD / 32);
        k_buildS0_split<<<g, dim3(32, 8)>>>(adj, invdr, S0h, S0l);
    }
    {
        dim3 g((KPAD + 255) / 256, NPADS);
        k_buildS1_split<<<g, 256>>>(adj, invdc, S1h, S1l);
    }

    k_buildX0<<<592, 256>>>(inputs, hx, X0);
    k_buildX0T<<<1024, 256>>>(inputs, hx, X0Th, X0Tl);
    k_zero_padsT<<<(PADELEMS + 255) / 256, 256>>>(X1aTh, X1aTl, X1bTh, X1bTl);

    dim3 ggrid(NPADS / NT, MPAD / MT, 2);  // 12 x 9 x 2

    // gconv 1 (gate)
    k_gemm_tc<<<ggrid, 256, SMEM_DYN>>>(X0Th, X0Tl, X0Th, X0Tl,
                                        S0h, S0l, S1h, S1l,
                                        nullptr, X1a, X1b,
                                        X1aTh, X1aTl, X1bTh, X1bTl, 1.f, 0.f);
    k_gemm_tc<<<ggrid, 256, SMEM_DYN>>>(X1aTh, X1aTl, X1bTh, X1bTl,
                                        S0h, S0l, S1h, S1l,
                                        X0, X2a, X2b,
                                        nullptr, nullptr, nullptr, nullptr, 2.f, -1.f);

    k_proj_gate<<<NNODES / 2, 128>>>(Wg, bg, hx, X0, X1a, X2a, X1b, X2b, X0, X0Th, X0Tl, ubuf);

    // gconv 2 (candidate)
    k_gemm_tc<<<ggrid, 256, SMEM_DYN>>>(X0Th, X0Tl, X0Th, X0Tl,
                                        S0h, S0l, S1h, S1l,
                                        nullptr, X1a, X1b,
                                        X1aTh, X1aTl, X1bTh, X1bTl, 1.f, 0.f);
    k_gemm_tc<<<ggrid, 256, SMEM_DYN>>>(X1aTh, X1aTl, X1bTh, X1bTl,
                                        S0h, S0l, S1h, S1l,
                                        X0, X2a, X2b,
                                        nullptr, nullptr, nullptr, nullptr, 2.f, -1.f);

    k_proj_cand<<<NNODES / 2, 64>>>(Wc, bc, hx, ubuf, X0, X1a, X2a, X1b, X2b, out);
}

// round 15
// speedup vs baseline: 1.1225x; 1.1225x over previous
#include <cuda_runtime.h>
#include <cuda_bf16.h>
#include <cstdint>
#include <cstddef>

#define NNODES 3000
#define NFEAT 2
#define NUNITS 64
#define BATCH 16
#define CCH (NFEAT + NUNITS)       // 66
#define NCOLS (CCH * BATCH)        // 1056
#define NGATE (2 * NUNITS)         // 128
#define HXSZ (NNODES * NUNITS)

#define KPAD 3008                  // 47 * 64
#define MPAD 1152
#define NPADS 3072
#define NCHUNK 47
#define MT 128
#define NT 256

#if defined(__CUDA_ARCH_FEAT_SM103_ALL) || defined(__CUDA_ARCH_FEAT_SM100_ALL) || \
    (defined(__CUDA_ARCH_SPECIFIC__) && (__CUDA_ARCH_SPECIFIC__ >= 1000))
#define HAS_TCGEN05 1
#else
#define HAS_TCGEN05 0
#endif

#define MMA_IDESC ((1u<<4)|(1u<<7)|(1u<<10)|((NT/8)<<17)|((MT/16)<<24))

__device__ __nv_bfloat16 g_S0h[(size_t)NPADS * KPAD];
__device__ __nv_bfloat16 g_S0l[(size_t)NPADS * KPAD];
__device__ __nv_bfloat16 g_S1h[(size_t)NPADS * KPAD];
__device__ __nv_bfloat16 g_S1l[(size_t)NPADS * KPAD];
__device__ __nv_bfloat16 g_X0Th[(size_t)MPAD * KPAD];
__device__ __nv_bfloat16 g_X0Tl[(size_t)MPAD * KPAD];
__device__ __nv_bfloat16 g_X1aTh[(size_t)MPAD * KPAD];
__device__ __nv_bfloat16 g_X1aTl[(size_t)MPAD * KPAD];
__device__ __nv_bfloat16 g_X1bTh[(size_t)MPAD * KPAD];
__device__ __nv_bfloat16 g_X1bTl[(size_t)MPAD * KPAD];
__device__ float g_X0[(size_t)NNODES * NCOLS];
__device__ float g_X1a[(size_t)NNODES * NCOLS];
__device__ float g_X2a[(size_t)NNODES * NCOLS];
__device__ float g_X1b[(size_t)NNODES * NCOLS];
__device__ float g_X2b[(size_t)NNODES * NCOLS];
__device__ float g_invdr[NNODES];
__device__ float g_dcol[NNODES];
__device__ float g_invdc[NNODES];
__device__ float g_u[(size_t)BATCH * NNODES * NUNITS];

__device__ __forceinline__ uint32_t smem_u32(const void* p) {
    uint32_t a;
    asm("{ .reg .u64 t; cvta.to.shared.u64 t, %1; cvt.u32.u64 %0, t; }" : "=r"(a) : "l"(p));
    return a;
}
static __device__ __forceinline__ uint32_t sw128(uint32_t off) { return off ^ ((off >> 3) & 0x70); }
static __device__ __forceinline__ void split_bf16(float v, __nv_bfloat16& h, __nv_bfloat16& l) {
    h = __float2bfloat16(v);
    l = __float2bfloat16(v - __bfloat162float(h));
}

#define CP_ASYNC16(dst, src) \
    asm volatile("cp.async.cg.shared.global [%0], [%1], 16;" :: "r"(dst), "l"(src) : "memory")
#define CP_COMMIT() asm volatile("cp.async.commit_group;" ::: "memory")
#define CP_WAIT1()  asm volatile("cp.async.wait_group 1;" ::: "memory")
#define CP_WAIT0()  asm volatile("cp.async.wait_group 0;" ::: "memory")

#if HAS_TCGEN05
__device__ __forceinline__ uint32_t elect_one() {
    uint32_t pred;
    asm volatile("{\n\t.reg .pred p;\n\telect.sync _|p, 0xFFFFFFFF;\n\tselp.b32 %0, 1, 0, p;\n\t}"
                 : "=r"(pred));
    return pred;
}
#define MBAR_INIT(a, c) asm volatile("mbarrier.init.shared.b64 [%0], %1;" :: "r"(a), "r"(c) : "memory")
#define MBAR_INVAL(a)   asm volatile("mbarrier.inval.shared.b64 [%0];" :: "r"(a) : "memory")
__device__ __forceinline__ void mbar_wait(uint32_t addr, uint32_t parity) {
    uint32_t done;
    asm volatile("{\n\t.reg .pred p;\n\t"
                 "mbarrier.try_wait.parity.acquire.cta.shared::cta.b64 p, [%1], %2;\n\t"
                 "selp.b32 %0, 1, 0, p;\n\t}"
                 : "=r"(done) : "r"(addr), "r"(parity) : "memory");
    if (!done) {
        asm volatile("{\n\t.reg .pred P1;\n\t"
                     "WL_%=:\n\t"
                     "mbarrier.try_wait.parity.acquire.cta.shared::cta.b64 P1, [%0], %1, 0x989680;\n\t"
                     "@P1 bra.uni WD_%=;\n\t"
                     "bra.uni WL_%=;\n\t"
                     "WD_%=:\n\t}"
                     :: "r"(addr), "r"(parity) : "memory");
    }
}
#define TC_ALLOC(sm, n)   asm volatile("tcgen05.alloc.cta_group::1.sync.aligned.shared::cta.b32 [%0], %1;" :: "r"(sm), "r"(n) : "memory")
#define TC_DEALLOC(t, n)  asm volatile("tcgen05.dealloc.cta_group::1.sync.aligned.b32 %0, %1;" :: "r"(t), "r"(n))
#define TC_RELINQ()       asm volatile("tcgen05.relinquish_alloc_permit.cta_group::1.sync.aligned;")
#define TC_COMMIT(mb)     asm volatile("tcgen05.commit.cta_group::1.mbarrier::arrive::one.shared::cluster.b64 [%0];" :: "r"(mb) : "memory")
#define TC_FENCE_AFTER()  asm volatile("tcgen05.fence::after_thread_sync;" ::: "memory")
#define TC_WAIT_LD()      asm volatile("tcgen05.wait::ld.sync.aligned;" ::: "memory")
#define FENCE_ASYNC()     asm volatile("fence.proxy.async.shared::cta;" ::: "memory")

__device__ __forceinline__ void mma_f16_ss(uint32_t d, uint64_t a, uint64_t b,
                                           uint32_t idesc, uint32_t en) {
    asm volatile("{\n\t.reg .pred p;\n\tsetp.ne.u32 p, %4, 0;\n\t"
                 "tcgen05.mma.cta_group::1.kind::f16 [%0], %1, %2, %3, {%5,%5,%5,%5}, p;\n\t}"
                 :: "r"(d), "l"(a), "l"(b), "r"(idesc), "r"(en), "r"(0u) : "memory");
}

#define LDTM_X32(r, addr) \
    asm volatile("tcgen05.ld.sync.aligned.32x32b.x32.b32 " \
        "{%0,%1,%2,%3,%4,%5,%6,%7,%8,%9,%10,%11,%12,%13,%14,%15," \
        "%16,%17,%18,%19,%20,%21,%22,%23,%24,%25,%26,%27,%28,%29,%30,%31}, [%32];" \
        : "=r"((r)[0]),"=r"((r)[1]),"=r"((r)[2]),"=r"((r)[3]),"=r"((r)[4]),"=r"((r)[5]), \
          "=r"((r)[6]),"=r"((r)[7]),"=r"((r)[8]),"=r"((r)[9]),"=r"((r)[10]),"=r"((r)[11]), \
          "=r"((r)[12]),"=r"((r)[13]),"=r"((r)[14]),"=r"((r)[15]),"=r"((r)[16]),"=r"((r)[17]), \
          "=r"((r)[18]),"=r"((r)[19]),"=r"((r)[20]),"=r"((r)[21]),"=r"((r)[22]),"=r"((r)[23]), \
          "=r"((r)[24]),"=r"((r)[25]),"=r"((r)[26]),"=r"((r)[27]),"=r"((r)[28]),"=r"((r)[29]), \
          "=r"((r)[30]),"=r"((r)[31]) : "r"(addr))

static __device__ __forceinline__ uint64_t make_desc(uint32_t addr) {
    const uint64_t base = (uint64_t(2) << 61) | (uint64_t(1) << 46) |
                          (uint64_t(64) << 32) | (uint64_t(1) << 16);
    return base | ((uint64_t)(addr >> 4) & 0x3FFF);
}
#else
__device__ __forceinline__ void ldm4(uint32_t* r, uint32_t addr) {
    asm volatile("ldmatrix.sync.aligned.m8n8.x4.shared.b16 {%0,%1,%2,%3}, [%4];"
                 : "=r"(r[0]), "=r"(r[1]), "=r"(r[2]), "=r"(r[3]) : "r"(addr));
}
__device__ __forceinline__ void mma16816(float* c, const uint32_t* a, uint32_t b0, uint32_t b1) {
    asm volatile("mma.sync.aligned.m16n8k16.row.col.f32.bf16.bf16.f32 "
                 "{%0,%1,%2,%3}, {%4,%5,%6,%7}, {%8,%9}, {%0,%1,%2,%3};"
                 : "+f"(c[0]), "+f"(c[1]), "+f"(c[2]), "+f"(c[3])
                 : "r"(a[0]), "r"(a[1]), "r"(a[2]), "r"(a[3]), "r"(b0), "r"(b1));
}
#endif

// ---------------- degree kernels ----------------
__global__ void k_rowsum(const float* __restrict__ A, float* __restrict__ invdr) {
    __shared__ float red[256];
    int r = blockIdx.x;
    float s = 0.f;
    for (int j = threadIdx.x; j < NNODES; j += 256) s += A[(size_t)r * NNODES + j];
    red[threadIdx.x] = s;
    __syncthreads();
    for (int w = 128; w > 0; w >>= 1) {
        if (threadIdx.x < w) red[threadIdx.x] += red[threadIdx.x + w];
        __syncthreads();
    }
    if (threadIdx.x == 0) {
        float d = red[0];
        invdr[r] = (d > 0.f) ? 1.f / d : 0.f;
    }
}
__global__ void k_zero_dcol(float* __restrict__ dcol) {
    int j = blockIdx.x * blockDim.x + threadIdx.x;
    if (j < NNODES) dcol[j] = 0.f;
}
__global__ void k_colsum_part(const float* __restrict__ A, float* __restrict__ dcol) {
    int j = blockIdx.x * blockDim.x + threadIdx.x;
    if (j >= NNODES) return;
    int r0 = blockIdx.y * 125;
    float s = 0.f;
    for (int r = r0; r < r0 + 125; r++) s += A[(size_t)r * NNODES + j];
    atomicAdd(&dcol[j], s);
}
__global__ void k_invert_dcol(const float* __restrict__ dcol, float* __restrict__ invdc) {
    int j = blockIdx.x * blockDim.x + threadIdx.x;
    if (j < NNODES) {
        float d = dcol[j];
        invdc[j] = (d > 0.f) ? 1.f / d : 0.f;
    }
}

// ---------------- supports ----------------
__global__ void k_buildS0_split(const float* __restrict__ A, const float* __restrict__ invdr,
                                __nv_bfloat16* __restrict__ Sh, __nv_bfloat16* __restrict__ Sl) {
    __shared__ float sm[32][33];
    int i0 = blockIdx.x * 32;
    int j0 = blockIdx.y * 32;
    int tx = threadIdx.x, ty = threadIdx.y;
#pragma unroll
    for (int r = 0; r < 4; r++) {
        int j = j0 + ty + r * 8;
        int i = i0 + tx;
        sm[ty + r * 8][tx] = (j < NNODES && i < NNODES) ? A[(size_t)j * NNODES + i] : 0.f;
    }
    __syncthreads();
#pragma unroll
    for (int r = 0; r < 4; r++) {
        int i = i0 + ty + r * 8;
        int j = j0 + tx;
        if (i < NPADS && j < KPAD) {
            float v = (i < NNODES && j < NNODES) ? sm[tx][ty + r * 8] * invdr[j] : 0.f;
            __nv_bfloat16 h, l;
            split_bf16(v, h, l);
            Sh[(size_t)i * KPAD + j] = h;
            Sl[(size_t)i * KPAD + j] = l;
        }
    }
}
__global__ void k_buildS1_split(const float* __restrict__ A, const float* __restrict__ invdc,
                                __nv_bfloat16* __restrict__ Sh, __nv_bfloat16* __restrict__ Sl) {
    int j = blockIdx.x * blockDim.x + threadIdx.x;
    int i = blockIdx.y;
    if (j >= KPAD) return;
    float v = (i < NNODES && j < NNODES) ? A[(size_t)i * NNODES + j] * invdc[j] : 0.f;
    __nv_bfloat16 h, l;
    split_bf16(v, h, l);
    Sh[(size_t)i * KPAD + j] = h;
    Sl[(size_t)i * KPAD + j] = l;
}

// ---------------- X0 builders ----------------
__global__ void k_buildX0(const float* __restrict__ inputs, const float* __restrict__ hx,
                          float* __restrict__ X0) {
    size_t total = (size_t)NNODES * NCOLS;
    for (size_t idx = (size_t)blockIdx.x * blockDim.x + threadIdx.x; idx < total;
         idx += (size_t)gridDim.x * blockDim.x) {
        int n = (int)(idx / NCOLS);
        int r = (int)(idx - (size_t)n * NCOLS);
        int c = r >> 4;
        int b = r & 15;
        float v = (c < NFEAT) ? inputs[(size_t)b * (NNODES * NFEAT) + n * NFEAT + c]
                              : hx[(size_t)b * HXSZ + n * NUNITS + (c - NFEAT)];
        X0[idx] = v;
    }
}
__global__ void k_buildX0T(const float* __restrict__ inputs, const float* __restrict__ hx,
                           __nv_bfloat16* __restrict__ Th, __nv_bfloat16* __restrict__ Tl) {
    size_t total = (size_t)MPAD * KPAD;
    for (size_t idx = (size_t)blockIdx.x * blockDim.x + threadIdx.x; idx < total;
         idx += (size_t)gridDim.x * blockDim.x) {
        int r = (int)(idx / KPAD);
        int n = (int)(idx - (size_t)r * KPAD);
        float v = 0.f;
        if (r < NCOLS && n < NNODES) {
            int c = r >> 4;
            int b = r & 15;
            v = (c < NFEAT) ? inputs[(size_t)b * (NNODES * NFEAT) + n * NFEAT + c]
                            : hx[(size_t)b * HXSZ + n * NUNITS + (c - NFEAT)];
        }
        __nv_bfloat16 h, l;
        split_bf16(v, h, l);
        Th[idx] = h;
        Tl[idx] = l;
    }
}
#define PADELEMS ((MPAD - NCOLS) * KPAD + NCOLS * 8)
__global__ void k_zero_padsT(__nv_bfloat16* a, __nv_bfloat16* b,
                             __nv_bfloat16* c, __nv_bfloat16* d) {
    int idx = blockIdx.x * blockDim.x + threadIdx.x;
    if (idx >= PADELEMS) return;
    size_t off;
    if (idx < (MPAD - NCOLS) * KPAD) {
        int r = NCOLS + idx / KPAD;
        int col = idx % KPAD;
        off = (size_t)r * KPAD + col;
    } else {
        int k = idx - (MPAD - NCOLS) * KPAD;
        int r = k >> 3;
        int col = NNODES + (k & 7);
        off = (size_t)r * KPAD + col;
    }
    __nv_bfloat16 z = __float2bfloat16(0.f);
    a[off] = z; b[off] = z; c[off] = z; d[off] = z;
}

// ---------------- main tensor-core GEMM (best-measured config) ----------------
#define ST_AH 0
#define ST_AL 16384
#define ST_BH 32768
#define ST_BL 65536
#define STAGE_SZ 98304
#define SMEM_DYN (2 * STAGE_SZ)
#define SST 264

__global__ __launch_bounds__(256, 1)
void k_gemm_tc(const __nv_bfloat16* __restrict__ Ah0, const __nv_bfloat16* __restrict__ Al0,
               const __nv_bfloat16* __restrict__ Ah1, const __nv_bfloat16* __restrict__ Al1,
               const __nv_bfloat16* __restrict__ Bh0, const __nv_bfloat16* __restrict__ Bl0,
               const __nv_bfloat16* __restrict__ Bh1, const __nv_bfloat16* __restrict__ Bl1,
               const float* __restrict__ Xprev,
               float* __restrict__ Yf0, float* __restrict__ Yf1,
               __nv_bfloat16* __restrict__ YTh0, __nv_bfloat16* __restrict__ YTl0,
               __nv_bfloat16* __restrict__ YTh1, __nv_bfloat16* __restrict__ YTl1,
               float alpha, float beta) {
    extern __shared__ __align__(1024) unsigned char dynsm[];
    const int t = threadIdx.x;
    const int m0 = blockIdx.y * MT;
    const int n0 = blockIdx.x * NT;
    const int z = blockIdx.z;
    const uint32_t dyn_u32 = smem_u32(dynsm);

    const __nv_bfloat16* Ahg = (z ? Ah1 : Ah0) + (size_t)m0 * KPAD;
    const __nv_bfloat16* Alg = (z ? Al1 : Al0) + (size_t)m0 * KPAD;
    const __nv_bfloat16* Bhg = (z ? Bh1 : Bh0) + (size_t)n0 * KPAD;
    const __nv_bfloat16* Blg = (z ? Bl1 : Bl0) + (size_t)n0 * KPAD;
    float* Yf = z ? Yf1 : Yf0;
    __nv_bfloat16* YTh = z ? YTh1 : YTh0;
    __nv_bfloat16* YTl = z ? YTl1 : YTl0;

    auto load_chunk = [&](int ck, uint32_t stg) {
        const int kb = ck * 64;
#pragma unroll
        for (int i = 0; i < 4; i++) {
            int idx = t + i * 256;
            int row = idx >> 3, seg = idx & 7;
            size_t go = (size_t)row * KPAD + kb + seg * 8;
            uint32_t so = sw128((uint32_t)(row * 128 + seg * 16));
            CP_ASYNC16(dyn_u32 + stg + ST_AH + so, Ahg + go);
            CP_ASYNC16(dyn_u32 + stg + ST_AL + so, Alg + go);
        }
#pragma unroll
        for (int i = 0; i < 8; i++) {
            int idx = t + i * 256;
            int row = idx >> 3, seg = idx & 7;
            size_t go = (size_t)row * KPAD + kb + seg * 8;
            uint32_t so = sw128((uint32_t)(row * 128 + seg * 16));
            CP_ASYNC16(dyn_u32 + stg + ST_BH + so, Bhg + go);
            CP_ASYNC16(dyn_u32 + stg + ST_BL + so, Blg + go);
        }
        CP_COMMIT();
    };

#if HAS_TCGEN05
    __shared__ uint32_t s_tmem;
    __shared__ __align__(8) uint64_t s_mbar[2];
    const uint32_t mbar0 = smem_u32(&s_mbar[0]);
    const uint32_t mbar1 = smem_u32(&s_mbar[1]);

    if ((t >> 5) == 0) TC_ALLOC(smem_u32(&s_tmem), 256);
    if (t == 0) {
        MBAR_INIT(mbar0, 1);
        MBAR_INIT(mbar1, 1);
    }
    __syncthreads();
    const uint32_t tmem = s_tmem;

    load_chunk(0, 0);
    load_chunk(1, STAGE_SZ);

    for (int k = 0; k < NCHUNK; k++) {
        const int s = k & 1;
        const uint32_t stage = s ? STAGE_SZ : 0;
        if (k == NCHUNK - 1) { CP_WAIT0(); } else { CP_WAIT1(); }
        __syncthreads();
        if ((t >> 5) == 0) {
            FENCE_ASYNC();
            if (elect_one()) {
                uint64_t dAh = make_desc(dyn_u32 + stage + ST_AH);
                uint64_t dAl = make_desc(dyn_u32 + stage + ST_AL);
                uint64_t dBh = make_desc(dyn_u32 + stage + ST_BH);
                uint64_t dBl = make_desc(dyn_u32 + stage + ST_BL);
#pragma unroll
                for (int ks = 0; ks < 4; ks++)
                    mma_f16_ss(tmem, dAh + ks * 2, dBh + ks * 2, MMA_IDESC,
                               (k != 0 || ks != 0) ? 1u : 0u);
#pragma unroll
                for (int ks = 0; ks < 4; ks++)
                    mma_f16_ss(tmem, dAh + ks * 2, dBl + ks * 2, MMA_IDESC, 1u);
#pragma unroll
                for (int ks = 0; ks < 4; ks++)
                    mma_f16_ss(tmem, dAl + ks * 2, dBh + ks * 2, MMA_IDESC, 1u);
                TC_COMMIT(s ? mbar1 : mbar0);
            }
        }
        if (k + 2 < NCHUNK) {
            mbar_wait(s ? mbar1 : mbar0, (k >> 1) & 1);
            load_chunk(k + 2, stage);
        }
    }
    mbar_wait(mbar0, 1);
    mbar_wait(mbar1, 0);
    TC_FENCE_AFTER();
    __syncthreads();

    const bool doT = (YTh != nullptr);
    const int w = t >> 5;
    const int chal = w >> 2;
    const int lane = t & 31;
    const int rl = (w & 3) * 32 + lane;
    const int m = m0 + rl;
    const bool vm = (m < NCOLS);
    __nv_bfloat16* shh = (__nv_bfloat16*)dynsm;
    __nv_bfloat16* shl = shh + 128 * SST;

    for (int cb = 0; cb < 4; cb++) {
        const int c0 = chal * 128 + cb * 32;
        uint32_t regs[32];
        LDTM_X32(regs, tmem + c0);
        TC_WAIT_LD();
#pragma unroll
        for (int j = 0; j < 32; j++) {
            int n = n0 + c0 + j;
            float y = alpha * __uint_as_float(regs[j]);
            bool vn = (n < NNODES);
            if (beta != 0.f && vm && vn) y += beta * Xprev[(size_t)n * NCOLS + m];
            if (vm && vn) Yf[(size_t)n * NCOLS + m] = y;
            if (doT) {
                __nv_bfloat16 h, l;
                split_bf16(y, h, l);
                shh[rl * SST + c0 + j] = h;
                shl[rl * SST + c0 + j] = l;
            }
        }
    }
    if (doT) {
        __syncthreads();
        int r = t >> 1, half = t & 1;
        int m2 = m0 + r;
        if (m2 < NCOLS) {
#pragma unroll
            for (int v = 0; v < 16; v++) {
                int nn = n0 + half * 128 + v * 8;
                int sidx = r * SST + half * 128 + v * 8;
                if (nn + 8 <= NNODES) {
                    *(uint4*)(YTh + (size_t)m2 * KPAD + nn) = *(uint4*)&shh[sidx];
                    *(uint4*)(YTl + (size_t)m2 * KPAD + nn) = *(uint4*)&shl[sidx];
                } else {
                    for (int e = 0; e < 8; e++)
                        if (nn + e < NNODES) {
                            YTh[(size_t)m2 * KPAD + nn + e] = shh[sidx + e];
                            YTl[(size_t)m2 * KPAD + nn + e] = shl[sidx + e];
                        }
                }
            }
        }
    }
    __syncthreads();
    if (t == 0) { MBAR_INVAL(mbar0); MBAR_INVAL(mbar1); }
    __syncthreads();
    if ((t >> 5) == 0) {
        TC_RELINQ();
        TC_DEALLOC(tmem, 256);
    }
#else
    const int lane = t & 31;
    const int warp = t >> 5;
    const int wm = warp & 1;
    const int wn = warp >> 1;
    const int lg = lane >> 3, lr = lane & 7;

    float acc[4][8][4];
#pragma unroll
    for (int i = 0; i < 4; i++)
#pragma unroll
        for (int j = 0; j < 8; j++)
#pragma unroll
            for (int e = 0; e < 4; e++) acc[i][j][e] = 0.f;

    for (int chunk = 0; chunk < NCHUNK; chunk++) {
        load_chunk(chunk, 0);
        CP_WAIT0();
        __syncthreads();
#pragma unroll
        for (int ks = 0; ks < 4; ks++) {
            uint32_t ah[4][4], al[4][4];
#pragma unroll
            for (int am = 0; am < 4; am++) {
                int row = wm * 64 + am * 16 + (lg & 1) * 8 + lr;
                int koff = ks * 32 + (lg >> 1) * 16;
                uint32_t so = sw128((uint32_t)(row * 128 + koff));
                ldm4(ah[am], dyn_u32 + ST_AH + so);
                ldm4(al[am], dyn_u32 + ST_AL + so);
            }
            uint32_t bh[4][4], bl[4][4];
#pragma unroll
            for (int p = 0; p < 4; p++) {
                int row = wn * 64 + p * 16 + (lg >> 1) * 8 + lr;
                int koff = ks * 32 + (lg & 1) * 16;
                uint32_t so = sw128((uint32_t)(row * 128 + koff));
                ldm4(bh[p], dyn_u32 + ST_BH + so);
                ldm4(bl[p], dyn_u32 + ST_BL + so);
            }
#pragma unroll
            for (int am = 0; am < 4; am++)
#pragma unroll
                for (int an = 0; an < 8; an++) {
                    int p = an >> 1, h = (an & 1) * 2;
                    mma16816(acc[am][an], ah[am], bh[p][h], bh[p][h + 1]);
                    mma16816(acc[am][an], ah[am], bl[p][h], bl[p][h + 1]);
                    mma16816(acc[am][an], al[am], bh[p][h], bh[p][h + 1]);
                }
        }
        __syncthreads();
    }

    const bool doT = (YTh != nullptr);
#pragma unroll
    for (int am = 0; am < 4; am++) {
#pragma unroll
        for (int an = 0; an < 8; an++) {
            int mrow = m0 + wm * 64 + am * 16 + (lane >> 2);
            int ncol = n0 + wn * 64 + an * 8 + (lane & 3) * 2;
#pragma unroll
            for (int h = 0; h < 2; h++) {
                int m = mrow + h * 8;
                if (m >= NCOLS) continue;
#pragma unroll
                for (int e = 0; e < 2; e++) {
                    int n = ncol + e;
                    if (n >= NNODES) continue;
                    float y = alpha * acc[am][an][h * 2 + e];
                    if (beta != 0.f) y += beta * Xprev[(size_t)n * NCOLS + m];
                    Yf[(size_t)n * NCOLS + m] = y;
                    if (doT) {
                        __nv_bfloat16 hh, ll;
                        split_bf16(y, hh, ll);
                        YTh[(size_t)m * KPAD + n] = hh;
                        YTl[(size_t)m * KPAD + n] = ll;
                    }
                }
            }
        }
    }
#endif
}

// ---------------- gate projection ----------------
__global__ void k_proj_gate(const float* __restrict__ Wg, const float* __restrict__ bg,
                            const float* __restrict__ hx,
                            const float* __restrict__ X0, const float* __restrict__ X1a,
                            const float* __restrict__ X2a, const float* __restrict__ X1b,
                            const float* __restrict__ X2b,
                            float* __restrict__ X0w,
                            __nv_bfloat16* __restrict__ X0Th, __nv_bfloat16* __restrict__ X0Tl,
                            float* __restrict__ ubuf) {
    __shared__ float sx[5][NCOLS];
    int n = blockIdx.x;
    const float* mats[5] = {X0, X1a, X2a, X1b, X2b};
    for (int tt = threadIdx.x; tt < 5 * NCOLS; tt += blockDim.x) {
        int m = tt / NCOLS;
        int idx = tt - m * NCOLS;
        sx[m][idx] = mats[m][(size_t)n * NCOLS + idx];
    }
    __syncthreads();

    int o = threadIdx.x;
    float acc[BATCH];
#pragma unroll
    for (int b = 0; b < BATCH; b++) acc[b] = bg[o];
    for (int c = 0; c < CCH; c++) {
#pragma unroll
        for (int m = 0; m < 5; m++) {
            float w = Wg[(size_t)(c * 5 + m) * NGATE + o];
#pragma unroll
            for (int b = 0; b < BATCH; b++) acc[b] += sx[m][c * 16 + b] * w;
        }
    }
#pragma unroll
    for (int b = 0; b < BATCH; b++) {
        float s = 1.f / (1.f + __expf(-acc[b]));
        if (o < NUNITS) {
            float h = hx[(size_t)b * HXSZ + n * NUNITS + o];
            float rh = s * h;
            X0w[(size_t)n * NCOLS + (NFEAT + o) * 16 + b] = rh;
            int rr = (NFEAT + o) * 16 + b;
            __nv_bfloat16 hi, lo;
            split_bf16(rh, hi, lo);
            X0Th[(size_t)rr * KPAD + n] = hi;
            X0Tl[(size_t)rr * KPAD + n] = lo;
        } else {
            ubuf[(size_t)b * HXSZ + n * NUNITS + (o - NUNITS)] = s;
        }
    }
}

// ---------------- cand projection + GRU combine ----------------
__global__ void k_proj_cand(const float* __restrict__ Wc, const float* __restrict__ bc,
                            const float* __restrict__ hx, const float* __restrict__ ubuf,
                            const float* __restrict__ X0, const float* __restrict__ X1a,
                            const float* __restrict__ X2a, const float* __restrict__ X1b,
                            const float* __restrict__ X2b,
                            float* __restrict__ out) {
    __shared__ float sx[5][NCOLS];
    int n = blockIdx.x;
    const float* mats[5] = {X0, X1a, X2a, X1b, X2b};
    for (int tt = threadIdx.x; tt < 5 * NCOLS; tt += blockDim.x) {
        int m = tt / NCOLS;
        int idx = tt - m * NCOLS;
        sx[m][idx] = mats[m][(size_t)n * NCOLS + idx];
    }
    __syncthreads();

    int o = threadIdx.x;
    float acc[BATCH];
#pragma unroll
    for (int b = 0; b < BATCH; b++) acc[b] = bc[o];
    for (int c = 0; c < CCH; c++) {
#pragma unroll
        for (int m = 0; m < 5; m++) {
            float w = Wc[(size_t)(c * 5 + m) * NUNITS + o];
#pragma unroll
            for (int b = 0; b < BATCH; b++) acc[b] += sx[m][c * 16 + b] * w;
        }
    }
#pragma unroll
    for (int b = 0; b < BATCH; b++) {
        float cc = tanhf(acc[b]);
        size_t i = (size_t)b * HXSZ + n * NUNITS + o;
        float u = ubuf[i];
        float h = hx[i];
        out[i] = u * h + (1.f - u) * cc;
    }
}

// ---------------- launch ----------------
extern "C" void kernel_launch(void* const* d_in, const int* in_sizes, int n_in,
                              void* d_out, int out_size) {
    const float* inputs = (const float*)d_in[0];
    const float* hx     = (const float*)d_in[1];
    const float* adj    = (const float*)d_in[2];
    const float* Wg     = (const float*)d_in[3];
    const float* bg     = (const float*)d_in[4];
    const float* Wc     = (const float*)d_in[5];
    const float* bc     = (const float*)d_in[6];
    float* out = (float*)d_out;

    __nv_bfloat16 *S0h, *S0l, *S1h, *S1l, *X0Th, *X0Tl, *X1aTh, *X1aTl, *X1bTh, *X1bTl;
    float *X0, *X1a, *X2a, *X1b, *X2b, *invdr, *dcol, *invdc, *ubuf;
    cudaGetSymbolAddress((void**)&S0h, g_S0h);
    cudaGetSymbolAddress((void**)&S0l, g_S0l);
    cudaGetSymbolAddress((void**)&S1h, g_S1h);
    cudaGetSymbolAddress((void**)&S1l, g_S1l);
    cudaGetSymbolAddress((void**)&X0Th, g_X0Th);
    cudaGetSymbolAddress((void**)&X0Tl, g_X0Tl);
    cudaGetSymbolAddress((void**)&X1aTh, g_X1aTh);
    cudaGetSymbolAddress((void**)&X1aTl, g_X1aTl);
    cudaGetSymbolAddress((void**)&X1bTh, g_X1bTh);
    cudaGetSymbolAddress((void**)&X1bTl, g_X1bTl);
    cudaGetSymbolAddress((void**)&X0, g_X0);
    cudaGetSymbolAddress((void**)&X1a, g_X1a);
    cudaGetSymbolAddress((void**)&X2a, g_X2a);
    cudaGetSymbolAddress((void**)&X1b, g_X1b);
    cudaGetSymbolAddress((void**)&X2b, g_X2b);
    cudaGetSymbolAddress((void**)&invdr, g_invdr);
    cudaGetSymbolAddress((void**)&dcol, g_dcol);
    cudaGetSymbolAddress((void**)&invdc, g_invdc);
    cudaGetSymbolAddress((void**)&ubuf, g_u);

    cudaFuncSetAttribute(k_gemm_tc, cudaFuncAttributeMaxDynamicSharedMemorySize, SMEM_DYN);

    k_rowsum<<<NNODES, 256>>>(adj, invdr);
    k_zero_dcol<<<(NNODES + 255) / 256, 256>>>(dcol);
    {
        dim3 g((NNODES + 255) / 256, 24);
        k_colsum_part<<<g, 256>>>(adj, dcol);
    }
    k_invert_dcol<<<(NNODES + 255) / 256, 256>>>(dcol, invdc);

    {
        dim3 g(NPADS / 32, KPAD / 32);
        k_buildS0_split<<<g, dim3(32, 8)>>>(adj, invdr, S0h, S0l);
    }
    {
        dim3 g((KPAD + 255) / 256, NPADS);
        k_buildS1_split<<<g, 256>>>(adj, invdc, S1h, S1l);
    }

    k_buildX0<<<592, 256>>>(inputs, hx, X0);
    k_buildX0T<<<1024, 256>>>(inputs, hx, X0Th, X0Tl);
    k_zero_padsT<<<(PADELEMS + 255) / 256, 256>>>(X1aTh, X1aTl, X1bTh, X1bTl);

    dim3 ggrid(NPADS / NT, MPAD / MT, 2);  // 12 x 9 x 2

    // gconv 1 (gate)
    k_gemm_tc<<<ggrid, 256, SMEM_DYN>>>(X0Th, X0Tl, X0Th, X0Tl,
                                        S0h, S0l, S1h, S1l,
                                        nullptr, X1a, X1b,
                                        X1aTh, X1aTl, X1bTh, X1bTl, 1.f, 0.f);
    k_gemm_tc<<<ggrid, 256, SMEM_DYN>>>(X1aTh, X1aTl, X1bTh, X1bTl,
                                        S0h, S0l, S1h, S1l,
                                        X0, X2a, X2b,
                                        nullptr, nullptr, nullptr, nullptr, 2.f, -1.f);

    k_proj_gate<<<NNODES, 128>>>(Wg, bg, hx, X0, X1a, X2a, X1b, X2b, X0, X0Th, X0Tl, ubuf);

    // gconv 2 (candidate)
    k_gemm_tc<<<ggrid, 256, SMEM_DYN>>>(X0Th, X0Tl, X0Th, X0Tl,
                                        S0h, S0l, S1h, S1l,
                                        nullptr, X1a, X1b,
                                        X1aTh, X1aTl, X1bTh, X1bTl, 1.f, 0.f);
    k_gemm_tc<<<ggrid, 256, SMEM_DYN>>>(X1aTh, X1aTl, X1bTh, X1bTl,
                                        S0h, S0l, S1h, S1l,
                                        X0, X2a, X2b,
                                        nullptr, nullptr, nullptr, nullptr, 2.f, -1.f);

    k_proj_cand<<<NNODES, 64>>>(Wc, bc, hx, ubuf, X0, X1a, X2a, X1b, X2b, out);
}

// round 16
// speedup vs baseline: 1.4059x; 1.2525x over previous
#include <cuda_runtime.h>
#include <cuda_bf16.h>
#include <cuda_fp8.h>
#include <cstdint>
#include <cstddef>

#define NNODES 3000
#define NFEAT 2
#define NUNITS 64
#define BATCH 16
#define CCH (NFEAT + NUNITS)       // 66
#define NCOLS (CCH * BATCH)        // 1056
#define NGATE (2 * NUNITS)         // 128
#define HXSZ (NNODES * NUNITS)

#define KPAD 3072                  // 24 * 128
#define MPAD 1152
#define NPADS 3072
#define NCHUNK 24
#define KCH 128                    // fp8 elements per chunk (128 bytes/row)
#define MT 128
#define NT 256

#define S_SCALE 1024.0f
#define X_SCALE 4.0f
#define X1_SCALE 32.0f

#if defined(__CUDA_ARCH_FEAT_SM103_ALL) || defined(__CUDA_ARCH_FEAT_SM100_ALL) || \
    (defined(__CUDA_ARCH_SPECIFIC__) && (__CUDA_ARCH_SPECIFIC__ >= 1000))
#define HAS_TCGEN05 1
#else
#define HAS_TCGEN05 0
#endif

// idesc kind::f8f6f4 (shared format with kind::f16): d=F32 (bit4), atype=btype=E4M3 (0)
#define MMA_IDESC ((1u<<4)|((NT/8)<<17)|((MT/16)<<24))

__device__ uint8_t g_S0h[(size_t)NPADS * KPAD];
__device__ uint8_t g_S0l[(size_t)NPADS * KPAD];
__device__ uint8_t g_S1h[(size_t)NPADS * KPAD];
__device__ uint8_t g_S1l[(size_t)NPADS * KPAD];
__device__ uint8_t g_X0Th[(size_t)MPAD * KPAD];
__device__ uint8_t g_X0Tl[(size_t)MPAD * KPAD];
__device__ uint8_t g_X1aTh[(size_t)MPAD * KPAD];
__device__ uint8_t g_X1aTl[(size_t)MPAD * KPAD];
__device__ uint8_t g_X1bTh[(size_t)MPAD * KPAD];
__device__ uint8_t g_X1bTl[(size_t)MPAD * KPAD];
__device__ float g_X0[(size_t)NNODES * NCOLS];
__device__ float g_X1a[(size_t)NNODES * NCOLS];
__device__ float g_X2a[(size_t)NNODES * NCOLS];
__device__ float g_X1b[(size_t)NNODES * NCOLS];
__device__ float g_X2b[(size_t)NNODES * NCOLS];
__device__ float g_invdr[NNODES];
__device__ float g_dcol[NNODES];
__device__ float g_invdc[NNODES];
__device__ float g_u[(size_t)BATCH * NNODES * NUNITS];

__device__ __forceinline__ uint32_t smem_u32(const void* p) {
    uint32_t a;
    asm("{ .reg .u64 t; cvta.to.shared.u64 t, %1; cvt.u32.u64 %0, t; }" : "=r"(a) : "l"(p));
    return a;
}
static __device__ __forceinline__ uint32_t sw128(uint32_t off) { return off ^ ((off >> 3) & 0x70); }

// scaled fp8 hi/lo split
static __device__ __forceinline__ void split_fp8(float v, uint8_t& h, uint8_t& l) {
    __nv_fp8_e4m3 a(v);
    float fa = float(a);
    __nv_fp8_e4m3 b(v - fa);
    h = a.__x;
    l = b.__x;
}
static __device__ __forceinline__ float fp8_val(uint8_t b) {
    __nv_fp8_e4m3 t;
    t.__x = b;
    return float(t);
}

#define CP_ASYNC16(dst, src) \
    asm volatile("cp.async.cg.shared.global [%0], [%1], 16;" :: "r"(dst), "l"(src) : "memory")
#define CP_COMMIT() asm volatile("cp.async.commit_group;" ::: "memory")
#define CP_WAIT1()  asm volatile("cp.async.wait_group 1;" ::: "memory")
#define CP_WAIT0()  asm volatile("cp.async.wait_group 0;" ::: "memory")

#if HAS_TCGEN05
__device__ __forceinline__ uint32_t elect_one() {
    uint32_t pred;
    asm volatile("{\n\t.reg .pred p;\n\telect.sync _|p, 0xFFFFFFFF;\n\tselp.b32 %0, 1, 0, p;\n\t}"
                 : "=r"(pred));
    return pred;
}
#define MBAR_INIT(a, c) asm volatile("mbarrier.init.shared.b64 [%0], %1;" :: "r"(a), "r"(c) : "memory")
#define MBAR_INVAL(a)   asm volatile("mbarrier.inval.shared.b64 [%0];" :: "r"(a) : "memory")
__device__ __forceinline__ void mbar_wait(uint32_t addr, uint32_t parity) {
    uint32_t done;
    asm volatile("{\n\t.reg .pred p;\n\t"
                 "mbarrier.try_wait.parity.acquire.cta.shared::cta.b64 p, [%1], %2;\n\t"
                 "selp.b32 %0, 1, 0, p;\n\t}"
                 : "=r"(done) : "r"(addr), "r"(parity) : "memory");
    if (!done) {
        asm volatile("{\n\t.reg .pred P1;\n\t"
                     "WL_%=:\n\t"
                     "mbarrier.try_wait.parity.acquire.cta.shared::cta.b64 P1, [%0], %1, 0x989680;\n\t"
                     "@P1 bra.uni WD_%=;\n\t"
                     "bra.uni WL_%=;\n\t"
                     "WD_%=:\n\t}"
                     :: "r"(addr), "r"(parity) : "memory");
    }
}
#define TC_ALLOC(sm, n)   asm volatile("tcgen05.alloc.cta_group::1.sync.aligned.shared::cta.b32 [%0], %1;" :: "r"(sm), "r"(n) : "memory")
#define TC_DEALLOC(t, n)  asm volatile("tcgen05.dealloc.cta_group::1.sync.aligned.b32 %0, %1;" :: "r"(t), "r"(n))
#define TC_RELINQ()       asm volatile("tcgen05.relinquish_alloc_permit.cta_group::1.sync.aligned;")
#define TC_COMMIT(mb)     asm volatile("tcgen05.commit.cta_group::1.mbarrier::arrive::one.shared::cluster.b64 [%0];" :: "r"(mb) : "memory")
#define TC_FENCE_AFTER()  asm volatile("tcgen05.fence::after_thread_sync;" ::: "memory")
#define TC_WAIT_LD()      asm volatile("tcgen05.wait::ld.sync.aligned;" ::: "memory")
#define FENCE_ASYNC()     asm volatile("fence.proxy.async.shared::cta;" ::: "memory")

__device__ __forceinline__ void mma_f8_ss(uint32_t d, uint64_t a, uint64_t b,
                                          uint32_t idesc, uint32_t en) {
    asm volatile("{\n\t.reg .pred p;\n\tsetp.ne.u32 p, %4, 0;\n\t"
                 "tcgen05.mma.cta_group::1.kind::f8f6f4 [%0], %1, %2, %3, {%5,%5,%5,%5}, p;\n\t}"
                 :: "r"(d), "l"(a), "l"(b), "r"(idesc), "r"(en), "r"(0u) : "memory");
}

#define LDTM_X32(r, addr) \
    asm volatile("tcgen05.ld.sync.aligned.32x32b.x32.b32 " \
        "{%0,%1,%2,%3,%4,%5,%6,%7,%8,%9,%10,%11,%12,%13,%14,%15," \
        "%16,%17,%18,%19,%20,%21,%22,%23,%24,%25,%26,%27,%28,%29,%30,%31}, [%32];" \
        : "=r"((r)[0]),"=r"((r)[1]),"=r"((r)[2]),"=r"((r)[3]),"=r"((r)[4]),"=r"((r)[5]), \
          "=r"((r)[6]),"=r"((r)[7]),"=r"((r)[8]),"=r"((r)[9]),"=r"((r)[10]),"=r"((r)[11]), \
          "=r"((r)[12]),"=r"((r)[13]),"=r"((r)[14]),"=r"((r)[15]),"=r"((r)[16]),"=r"((r)[17]), \
          "=r"((r)[18]),"=r"((r)[19]),"=r"((r)[20]),"=r"((r)[21]),"=r"((r)[22]),"=r"((r)[23]), \
          "=r"((r)[24]),"=r"((r)[25]),"=r"((r)[26]),"=r"((r)[27]),"=r"((r)[28]),"=r"((r)[29]), \
          "=r"((r)[30]),"=r"((r)[31]) : "r"(addr))

static __device__ __forceinline__ uint64_t make_desc(uint32_t addr) {
    const uint64_t base = (uint64_t(2) << 61) | (uint64_t(1) << 46) |
                          (uint64_t(64) << 32) | (uint64_t(1) << 16);
    return base | ((uint64_t)(addr >> 4) & 0x3FFF);
}
#endif

// ---------------- degree kernels ----------------
__global__ void k_rowsum(const float* __restrict__ A, float* __restrict__ invdr) {
    __shared__ float red[256];
    int r = blockIdx.x;
    float s = 0.f;
    for (int j = threadIdx.x; j < NNODES; j += 256) s += A[(size_t)r * NNODES + j];
    red[threadIdx.x] = s;
    __syncthreads();
    for (int w = 128; w > 0; w >>= 1) {
        if (threadIdx.x < w) red[threadIdx.x] += red[threadIdx.x + w];
        __syncthreads();
    }
    if (threadIdx.x == 0) {
        float d = red[0];
        invdr[r] = (d > 0.f) ? 1.f / d : 0.f;
    }
}
__global__ void k_zero_dcol(float* __restrict__ dcol) {
    int j = blockIdx.x * blockDim.x + threadIdx.x;
    if (j < NNODES) dcol[j] = 0.f;
}
__global__ void k_colsum_part(const float* __restrict__ A, float* __restrict__ dcol) {
    int j = blockIdx.x * blockDim.x + threadIdx.x;
    if (j >= NNODES) return;
    int r0 = blockIdx.y * 125;
    float s = 0.f;
    for (int r = r0; r < r0 + 125; r++) s += A[(size_t)r * NNODES + j];
    atomicAdd(&dcol[j], s);
}
__global__ void k_invert_dcol(const float* __restrict__ dcol, float* __restrict__ invdc) {
    int j = blockIdx.x * blockDim.x + threadIdx.x;
    if (j < NNODES) {
        float d = dcol[j];
        invdc[j] = (d > 0.f) ? 1.f / d : 0.f;
    }
}

// ---------------- supports (fp8 hi/lo, scaled) ----------------
__global__ void k_buildS0_split(const float* __restrict__ A, const float* __restrict__ invdr,
                                uint8_t* __restrict__ Sh, uint8_t* __restrict__ Sl) {
    __shared__ float sm[32][33];
    int i0 = blockIdx.x * 32;
    int j0 = blockIdx.y * 32;
    int tx = threadIdx.x, ty = threadIdx.y;
#pragma unroll
    for (int r = 0; r < 4; r++) {
        int j = j0 + ty + r * 8;
        int i = i0 + tx;
        sm[ty + r * 8][tx] = (j < NNODES && i < NNODES) ? A[(size_t)j * NNODES + i] : 0.f;
    }
    __syncthreads();
#pragma unroll
    for (int r = 0; r < 4; r++) {
        int i = i0 + ty + r * 8;
        int j = j0 + tx;
        if (i < NPADS && j < KPAD) {
            float v = (i < NNODES && j < NNODES) ? sm[tx][ty + r * 8] * invdr[j] * S_SCALE : 0.f;
            uint8_t h, l;
            split_fp8(v, h, l);
            Sh[(size_t)i * KPAD + j] = h;
            Sl[(size_t)i * KPAD + j] = l;
        }
    }
}
__global__ void k_buildS1_split(const float* __restrict__ A, const float* __restrict__ invdc,
                                uint8_t* __restrict__ Sh, uint8_t* __restrict__ Sl) {
    int j = blockIdx.x * blockDim.x + threadIdx.x;
    int i = blockIdx.y;
    if (j >= KPAD) return;
    float v = (i < NNODES && j < NNODES) ? A[(size_t)i * NNODES + j] * invdc[j] * S_SCALE : 0.f;
    uint8_t h, l;
    split_fp8(v, h, l);
    Sh[(size_t)i * KPAD + j] = h;
    Sl[(size_t)i * KPAD + j] = l;
}

// ---------------- X0 builders ----------------
__global__ void k_buildX0(const float* __restrict__ inputs, const float* __restrict__ hx,
                          float* __restrict__ X0) {
    size_t total = (size_t)NNODES * NCOLS;
    for (size_t idx = (size_t)blockIdx.x * blockDim.x + threadIdx.x; idx < total;
         idx += (size_t)gridDim.x * blockDim.x) {
        int n = (int)(idx / NCOLS);
        int r = (int)(idx - (size_t)n * NCOLS);
        int c = r >> 4;
        int b = r & 15;
        float v = (c < NFEAT) ? inputs[(size_t)b * (NNODES * NFEAT) + n * NFEAT + c]
                              : hx[(size_t)b * HXSZ + n * NUNITS + (c - NFEAT)];
        X0[idx] = v;
    }
}
// covers full MPAD x KPAD (zeros pads)
__global__ void k_buildX0T(const float* __restrict__ inputs, const float* __restrict__ hx,
                           uint8_t* __restrict__ Th, uint8_t* __restrict__ Tl) {
    size_t total = (size_t)MPAD * KPAD;
    for (size_t idx = (size_t)blockIdx.x * blockDim.x + threadIdx.x; idx < total;
         idx += (size_t)gridDim.x * blockDim.x) {
        int r = (int)(idx / KPAD);
        int n = (int)(idx - (size_t)r * KPAD);
        float v = 0.f;
        if (r < NCOLS && n < NNODES) {
            int c = r >> 4;
            int b = r & 15;
            v = (c < NFEAT) ? inputs[(size_t)b * (NNODES * NFEAT) + n * NFEAT + c]
                            : hx[(size_t)b * HXSZ + n * NUNITS + (c - NFEAT)];
            v *= X_SCALE;
        }
        uint8_t h, l;
        split_fp8(v, h, l);
        Th[idx] = h;
        Tl[idx] = l;
    }
}
#define COLPAD (KPAD - NNODES)     // 72
#define PADELEMS ((MPAD - NCOLS) * KPAD + NCOLS * COLPAD)
__global__ void k_zero_padsT(uint8_t* a, uint8_t* b, uint8_t* c, uint8_t* d) {
    int idx = blockIdx.x * blockDim.x + threadIdx.x;
    if (idx >= PADELEMS) return;
    size_t off;
    if (idx < (MPAD - NCOLS) * KPAD) {
        int r = NCOLS + idx / KPAD;
        int col = idx % KPAD;
        off = (size_t)r * KPAD + col;
    } else {
        int k = idx - (MPAD - NCOLS) * KPAD;
        int r = k / COLPAD;
        int col = NNODES + (k % COLPAD);
        off = (size_t)r * KPAD + col;
    }
    a[off] = 0; b[off] = 0; c[off] = 0; d[off] = 0;
}

// ---------------- main tensor-core GEMM (fp8 e4m3 hi/lo, 4 products) ----------------
#define ST_AH 0
#define ST_AL 16384
#define ST_BH 32768
#define ST_BL 65536
#define STAGE_SZ 98304
#define SMEM_DYN (2 * STAGE_SZ)
#define SST 272

__global__ __launch_bounds__(256, 1)
void k_gemm_tc(const uint8_t* __restrict__ Ah0, const uint8_t* __restrict__ Al0,
               const uint8_t* __restrict__ Ah1, const uint8_t* __restrict__ Al1,
               const uint8_t* __restrict__ Bh0, const uint8_t* __restrict__ Bl0,
               const uint8_t* __restrict__ Bh1, const uint8_t* __restrict__ Bl1,
               const float* __restrict__ Xprev,
               float* __restrict__ Yf0, float* __restrict__ Yf1,
               uint8_t* __restrict__ YTh0, uint8_t* __restrict__ YTl0,
               uint8_t* __restrict__ YTh1, uint8_t* __restrict__ YTl1,
               float alpha, float beta, float outscale) {
    extern __shared__ __align__(1024) unsigned char dynsm[];
    const int t = threadIdx.x;
    const int m0 = blockIdx.y * MT;
    const int n0 = blockIdx.x * NT;
    const int z = blockIdx.z;
    const uint32_t dyn_u32 = smem_u32(dynsm);

    const uint8_t* Ahg = (z ? Ah1 : Ah0) + (size_t)m0 * KPAD;
    const uint8_t* Alg = (z ? Al1 : Al0) + (size_t)m0 * KPAD;
    const uint8_t* Bhg = (z ? Bh1 : Bh0) + (size_t)n0 * KPAD;
    const uint8_t* Blg = (z ? Bl1 : Bl0) + (size_t)n0 * KPAD;
    float* Yf = z ? Yf1 : Yf0;
    uint8_t* YTh = z ? YTh1 : YTh0;
    uint8_t* YTl = z ? YTl1 : YTl0;

    // one K=128 chunk: A 128 rows x 128B, B 256 rows x 128B, hi+lo (96 KB total)
    auto load_chunk = [&](int ck, uint32_t stg) {
        const int kb = ck * KCH;
#pragma unroll
        for (int i = 0; i < 4; i++) {
            int idx = t + i * 256;
            int row = idx >> 3, seg = idx & 7;
            size_t go = (size_t)row * KPAD + kb + seg * 16;
            uint32_t so = sw128((uint32_t)(row * 128 + seg * 16));
            CP_ASYNC16(dyn_u32 + stg + ST_AH + so, Ahg + go);
            CP_ASYNC16(dyn_u32 + stg + ST_AL + so, Alg + go);
        }
#pragma unroll
        for (int i = 0; i < 8; i++) {
            int idx = t + i * 256;
            int row = idx >> 3, seg = idx & 7;
            size_t go = (size_t)row * KPAD + kb + seg * 16;
            uint32_t so = sw128((uint32_t)(row * 128 + seg * 16));
            CP_ASYNC16(dyn_u32 + stg + ST_BH + so, Bhg + go);
            CP_ASYNC16(dyn_u32 + stg + ST_BL + so, Blg + go);
        }
        CP_COMMIT();
    };

#if HAS_TCGEN05
    __shared__ uint32_t s_tmem;
    __shared__ __align__(8) uint64_t s_mbar[2];
    const uint32_t mbar0 = smem_u32(&s_mbar[0]);
    const uint32_t mbar1 = smem_u32(&s_mbar[1]);

    if ((t >> 5) == 0) TC_ALLOC(smem_u32(&s_tmem), 256);
    if (t == 0) {
        MBAR_INIT(mbar0, 1);
        MBAR_INIT(mbar1, 1);
    }
    __syncthreads();
    const uint32_t tmem = s_tmem;

    load_chunk(0, 0);
    load_chunk(1, STAGE_SZ);

    for (int k = 0; k < NCHUNK; k++) {
        const int s = k & 1;
        const uint32_t stage = s ? STAGE_SZ : 0;
        if (k == NCHUNK - 1) { CP_WAIT0(); } else { CP_WAIT1(); }
        __syncthreads();
        if ((t >> 5) == 0) {
            FENCE_ASYNC();
            if (elect_one()) {
                uint64_t dAh = make_desc(dyn_u32 + stage + ST_AH);
                uint64_t dAl = make_desc(dyn_u32 + stage + ST_AL);
                uint64_t dBh = make_desc(dyn_u32 + stage + ST_BH);
                uint64_t dBl = make_desc(dyn_u32 + stage + ST_BL);
                // 4 K-steps of 32 fp8 (32B = +2 desc units each), 4 products
#pragma unroll
                for (int ks = 0; ks < 4; ks++)
                    mma_f8_ss(tmem, dAh + ks * 2, dBh + ks * 2, MMA_IDESC,
                              (k != 0 || ks != 0) ? 1u : 0u);
#pragma unroll
                for (int ks = 0; ks < 4; ks++)
                    mma_f8_ss(tmem, dAh + ks * 2, dBl + ks * 2, MMA_IDESC, 1u);
#pragma unroll
                for (int ks = 0; ks < 4; ks++)
                    mma_f8_ss(tmem, dAl + ks * 2, dBh + ks * 2, MMA_IDESC, 1u);
#pragma unroll
                for (int ks = 0; ks < 4; ks++)
                    mma_f8_ss(tmem, dAl + ks * 2, dBl + ks * 2, MMA_IDESC, 1u);
                TC_COMMIT(s ? mbar1 : mbar0);
            }
        }
        if (k + 2 < NCHUNK) {
            mbar_wait(s ? mbar1 : mbar0, (k >> 1) & 1);
            load_chunk(k + 2, stage);
        }
    }
    // NCHUNK=24: mbar0 12 commits -> phase 11 parity 1; mbar1 12 commits -> parity 1
    mbar_wait(mbar0, 1);
    mbar_wait(mbar1, 1);
    TC_FENCE_AFTER();
    __syncthreads();

    const bool doT = (YTh != nullptr);
    const int w = t >> 5;
    const int chal = w >> 2;
    const int lane = t & 31;
    const int rl = (w & 3) * 32 + lane;
    const int m = m0 + rl;
    const bool vm = (m < NCOLS);
    uint8_t* shh = (uint8_t*)dynsm;
    uint8_t* shl = shh + 128 * SST;

    for (int cb = 0; cb < 4; cb++) {
        const int c0 = chal * 128 + cb * 32;
        uint32_t regs[32];
        LDTM_X32(regs, tmem + c0);
        TC_WAIT_LD();
#pragma unroll
        for (int j = 0; j < 32; j++) {
            int n = n0 + c0 + j;
            float y = alpha * __uint_as_float(regs[j]);
            bool vn = (n < NNODES);
            if (beta != 0.f && vm && vn) y += beta * Xprev[(size_t)n * NCOLS + m];
            if (vm && vn) Yf[(size_t)n * NCOLS + m] = y;
            if (doT) {
                uint8_t h, l;
                split_fp8(y * outscale, h, l);
                shh[rl * SST + c0 + j] = h;
                shl[rl * SST + c0 + j] = l;
            }
        }
    }
    if (doT) {
        __syncthreads();
        int r = t >> 1, half = t & 1;
        int m2 = m0 + r;
        if (m2 < NCOLS) {
#pragma unroll
            for (int v = 0; v < 8; v++) {
                int nn = n0 + half * 128 + v * 16;
                int sidx = r * SST + half * 128 + v * 16;
                if (nn + 16 <= NNODES) {
                    *(uint4*)(YTh + (size_t)m2 * KPAD + nn) = *(uint4*)&shh[sidx];
                    *(uint4*)(YTl + (size_t)m2 * KPAD + nn) = *(uint4*)&shl[sidx];
                } else {
                    for (int e = 0; e < 16; e++)
                        if (nn + e < NNODES) {
                            YTh[(size_t)m2 * KPAD + nn + e] = shh[sidx + e];
                            YTl[(size_t)m2 * KPAD + nn + e] = shl[sidx + e];
                        }
                }
            }
        }
    }
    __syncthreads();
    if (t == 0) { MBAR_INVAL(mbar0); MBAR_INVAL(mbar1); }
    __syncthreads();
    if ((t >> 5) == 0) {
        TC_RELINQ();
        TC_DEALLOC(tmem, 256);
    }
#else
    // portable fallback (compile-only; sm_103a cubin runs at runtime): scalar fp32
    (void)load_chunk;
    const bool doT = (YTh != nullptr);
    for (int idx = t; idx < MT * NT; idx += 256) {
        int mi = idx / NT, nj = idx - mi * NT;
        int m = m0 + mi, n = n0 + nj;
        if (m >= NCOLS || n >= NNODES) continue;
        float acc = 0.f;
        for (int k = 0; k < KPAD; k++) {
            float av = fp8_val(Ahg[(size_t)(m - m0 + 0) * 0 + (size_t)mi * KPAD + k]) +
                       fp8_val(Alg[(size_t)mi * KPAD + k]);
            float bv = fp8_val(Bhg[(size_t)nj * KPAD + k]) +
                       fp8_val(Blg[(size_t)nj * KPAD + k]);
            acc += av * bv;
        }
        float y = alpha * acc;
        if (beta != 0.f) y += beta * Xprev[(size_t)n * NCOLS + m];
        Yf[(size_t)n * NCOLS + m] = y;
        if (doT) {
            uint8_t h, l;
            split_fp8(y * outscale, h, l);
            YTh[(size_t)m * KPAD + n] = h;
            YTl[(size_t)m * KPAD + n] = l;
        }
    }
#endif
}

// ---------------- gate projection ----------------
__global__ void k_proj_gate(const float* __restrict__ Wg, const float* __restrict__ bg,
                            const float* __restrict__ hx,
                            const float* __restrict__ X0, const float* __restrict__ X1a,
                            const float* __restrict__ X2a, const float* __restrict__ X1b,
                            const float* __restrict__ X2b,
                            float* __restrict__ X0w,
                            uint8_t* __restrict__ X0Th, uint8_t* __restrict__ X0Tl,
                            float* __restrict__ ubuf) {
    __shared__ float sx[5][NCOLS];
    int n = blockIdx.x;
    const float* mats[5] = {X0, X1a, X2a, X1b, X2b};
    for (int tt = threadIdx.x; tt < 5 * NCOLS; tt += blockDim.x) {
        int m = tt / NCOLS;
        int idx = tt - m * NCOLS;
        sx[m][idx] = mats[m][(size_t)n * NCOLS + idx];
    }
    __syncthreads();

    int o = threadIdx.x;
    float acc[BATCH];
#pragma unroll
    for (int b = 0; b < BATCH; b++) acc[b] = bg[o];
    for (int c = 0; c < CCH; c++) {
#pragma unroll
        for (int m = 0; m < 5; m++) {
            float w = Wg[(size_t)(c * 5 + m) * NGATE + o];
#pragma unroll
            for (int b = 0; b < BATCH; b++) acc[b] += sx[m][c * 16 + b] * w;
        }
    }
#pragma unroll
    for (int b = 0; b < BATCH; b++) {
        float s = 1.f / (1.f + __expf(-acc[b]));
        if (o < NUNITS) {
            float h = hx[(size_t)b * HXSZ + n * NUNITS + o];
            float rh = s * h;
            X0w[(size_t)n * NCOLS + (NFEAT + o) * 16 + b] = rh;
            int rr = (NFEAT + o) * 16 + b;
            uint8_t hi, lo;
            split_fp8(rh * X_SCALE, hi, lo);
            X0Th[(size_t)rr * KPAD + n] = hi;
            X0Tl[(size_t)rr * KPAD + n] = lo;
        } else {
            ubuf[(size_t)b * HXSZ + n * NUNITS + (o - NUNITS)] = s;
        }
    }
}

// ---------------- cand projection + GRU combine ----------------
__global__ void k_proj_cand(const float* __restrict__ Wc, const float* __restrict__ bc,
                            const float* __restrict__ hx, const float* __restrict__ ubuf,
                            const float* __restrict__ X0, const float* __restrict__ X1a,
                            const float* __restrict__ X2a, const float* __restrict__ X1b,
                            const float* __restrict__ X2b,
                            float* __restrict__ out) {
    __shared__ float sx[5][NCOLS];
    int n = blockIdx.x;
    const float* mats[5] = {X0, X1a, X2a, X1b, X2b};
    for (int tt = threadIdx.x; tt < 5 * NCOLS; tt += blockDim.x) {
        int m = tt / NCOLS;
        int idx = tt - m * NCOLS;
        sx[m][idx] = mats[m][(size_t)n * NCOLS + idx];
    }
    __syncthreads();

    int o = threadIdx.x;
    float acc[BATCH];
#pragma unroll
    for (int b = 0; b < BATCH; b++) acc[b] = bc[o];
    for (int c = 0; c < CCH; c++) {
#pragma unroll
        for (int m = 0; m < 5; m++) {
            float w = Wc[(size_t)(c * 5 + m) * NUNITS + o];
#pragma unroll
            for (int b = 0; b < BATCH; b++) acc[b] += sx[m][c * 16 + b] * w;
        }
    }
#pragma unroll
    for (int b = 0; b < BATCH; b++) {
        float cc = tanhf(acc[b]);
        size_t i = (size_t)b * HXSZ + n * NUNITS + o;
        float u = ubuf[i];
        float h = hx[i];
        out[i] = u * h + (1.f - u) * cc;
    }
}

// ---------------- launch ----------------
extern "C" void kernel_launch(void* const* d_in, const int* in_sizes, int n_in,
                              void* d_out, int out_size) {
    const float* inputs = (const float*)d_in[0];
    const float* hx     = (const float*)d_in[1];
    const float* adj    = (const float*)d_in[2];
    const float* Wg     = (const float*)d_in[3];
    const float* bg     = (const float*)d_in[4];
    const float* Wc     = (const float*)d_in[5];
    const float* bc     = (const float*)d_in[6];
    float* out = (float*)d_out;

    uint8_t *S0h, *S0l, *S1h, *S1l, *X0Th, *X0Tl, *X1aTh, *X1aTl, *X1bTh, *X1bTl;
    float *X0, *X1a, *X2a, *X1b, *X2b, *invdr, *dcol, *invdc, *ubuf;
    cudaGetSymbolAddress((void**)&S0h, g_S0h);
    cudaGetSymbolAddress((void**)&S0l, g_S0l);
    cudaGetSymbolAddress((void**)&S1h, g_S1h);
    cudaGetSymbolAddress((void**)&S1l, g_S1l);
    cudaGetSymbolAddress((void**)&X0Th, g_X0Th);
    cudaGetSymbolAddress((void**)&X0Tl, g_X0Tl);
    cudaGetSymbolAddress((void**)&X1aTh, g_X1aTh);
    cudaGetSymbolAddress((void**)&X1aTl, g_X1aTl);
    cudaGetSymbolAddress((void**)&X1bTh, g_X1bTh);
    cudaGetSymbolAddress((void**)&X1bTl, g_X1bTl);
    cudaGetSymbolAddress((void**)&X0, g_X0);
    cudaGetSymbolAddress((void**)&X1a, g_X1a);
    cudaGetSymbolAddress((void**)&X2a, g_X2a);
    cudaGetSymbolAddress((void**)&X1b, g_X1b);
    cudaGetSymbolAddress((void**)&X2b, g_X2b);
    cudaGetSymbolAddress((void**)&invdr, g_invdr);
    cudaGetSymbolAddress((void**)&dcol, g_dcol);
    cudaGetSymbolAddress((void**)&invdc, g_invdc);
    cudaGetSymbolAddress((void**)&ubuf, g_u);

    cudaFuncSetAttribute(k_gemm_tc, cudaFuncAttributeMaxDynamicSharedMemorySize, SMEM_DYN);

    k_rowsum<<<NNODES, 256>>>(adj, invdr);
    k_zero_dcol<<<(NNODES + 255) / 256, 256>>>(dcol);
    {
        dim3 g((NNODES + 255) / 256, 24);
        k_colsum_part<<<g, 256>>>(adj, dcol);
    }
    k_invert_dcol<<<(NNODES + 255) / 256, 256>>>(dcol, invdc);

    {
        dim3 g(NPADS / 32, KPAD / 32);
        k_buildS0_split<<<g, dim3(32, 8)>>>(adj, invdr, S0h, S0l);
    }
    {
        dim3 g((KPAD + 255) / 256, NPADS);
        k_buildS1_split<<<g, 256>>>(adj, invdc, S1h, S1l);
    }

    k_buildX0<<<592, 256>>>(inputs, hx, X0);
    k_buildX0T<<<1024, 256>>>(inputs, hx, X0Th, X0Tl);
    k_zero_padsT<<<(PADELEMS + 255) / 256, 256>>>(X1aTh, X1aTl, X1bTh, X1bTl);

    dim3 ggrid(NPADS / NT, MPAD / MT, 2);  // 12 x 9 x 2

    const float a1 = 1.f / (S_SCALE * X_SCALE);      // dequant for X1 = S @ x0
    const float a2 = 2.f / (S_SCALE * X1_SCALE);     // dequant for X2 = 2 S X1 - X0

    // gconv 1 (gate)
    k_gemm_tc<<<ggrid, 256, SMEM_DYN>>>(X0Th, X0Tl, X0Th, X0Tl,
                                        S0h, S0l, S1h, S1l,
                                        nullptr, X1a, X1b,
                                        X1aTh, X1aTl, X1bTh, X1bTl,
                                        a1, 0.f, X1_SCALE);
    k_gemm_tc<<<ggrid, 256, SMEM_DYN>>>(X1aTh, X1aTl, X1bTh, X1bTl,
                                        S0h, S0l, S1h, S1l,
                                        X0, X2a, X2b,
                                        nullptr, nullptr, nullptr, nullptr,
                                        a2, -1.f, 1.f);

    k_proj_gate<<<NNODES, 128>>>(Wg, bg, hx, X0, X1a, X2a, X1b, X2b, X0, X0Th, X0Tl, ubuf);

    // gconv 2 (candidate)
    k_gemm_tc<<<ggrid, 256, SMEM_DYN>>>(X0Th, X0Tl, X0Th, X0Tl,
                                        S0h, S0l, S1h, S1l,
                                        nullptr, X1a, X1b,
                                        X1aTh, X1aTl, X1bTh, X1bTl,
                                        a1, 0.f, X1_SCALE);
    k_gemm_tc<<<ggrid, 256, SMEM_DYN>>>(X1aTh, X1aTl, X1bTh, X1bTl,
                                        S0h, S0l, S1h, S1l,
                                        X0, X2a, X2b,
                                        nullptr, nullptr, nullptr, nullptr,
                                        a2, -1.f, 1.f);

    k_proj_cand<<<NNODES, 64>>>(Wc, bc, hx, ubuf, X0, X1a, X2a, X1b, X2b, out);
}